// round 4
// baseline (speedup 1.0000x reference)
#include <cuda_runtime.h>
#include <math.h>

#define N_MAX   100000
#define IN_DIM  128
#define HID     32

// ---- scratch (no allocation allowed), 16B-aligned for float4 access ----
__device__ __align__(16) float g_bufA[(size_t)N_MAX * HID];   // hW (layer1), then hW2 (layer2)
__device__ __align__(16) float g_bufB[(size_t)N_MAX * HID];   // agg1
__device__ __align__(16) float g_bufC[(size_t)N_MAX * HID];   // agg2
__device__ float g_dinv[N_MAX];                 // deg, then rsqrt(deg)
__device__ float g_scores[N_MAX + 1];
__device__ float g_max_v;
__device__ float g_sum_v;

// ============ degree ============
__global__ void k_deg_init(int N) {
    int i = blockIdx.x * blockDim.x + threadIdx.x;
    if (i < N) g_dinv[i] = 1.0f;               // self-loop
    if (i == 0) { g_max_v = -INFINITY; g_sum_v = 0.0f; }
}

__global__ void k_deg_acc(const int* __restrict__ dst, int E) {
    int i = blockIdx.x * blockDim.x + threadIdx.x;
    if (i < E) atomicAdd(&g_dinv[dst[i]], 1.0f);
}

__global__ void k_rsqrt(int N) {
    int i = blockIdx.x * blockDim.x + threadIdx.x;
    if (i < N) g_dinv[i] = rsqrtf(g_dinv[i]);
}

// ============ GEMM1: hW = x @ W1 ; agg1 = dinv^2 * hW (self-loop fused) ============
__global__ void k_gemm1(const float* __restrict__ x, const float* __restrict__ W1, int N) {
    __shared__ float sW[IN_DIM * HID];          // 16 KB
    for (int i = threadIdx.x; i < IN_DIM * HID; i += blockDim.x) sW[i] = W1[i];
    __syncthreads();

    int warp = threadIdx.x >> 5, lane = threadIdx.x & 31;
    for (int n = blockIdx.x * 8 + warp; n < N; n += gridDim.x * 8) {
        const float4* xr = (const float4*)(x + (size_t)n * IN_DIM);
        float acc = 0.0f;
        #pragma unroll
        for (int k4 = 0; k4 < IN_DIM / 4; k4++) {
            float4 xv = xr[k4];                 // broadcast within warp
            acc = fmaf(xv.x, sW[(k4 * 4 + 0) * HID + lane], acc);
            acc = fmaf(xv.y, sW[(k4 * 4 + 1) * HID + lane], acc);
            acc = fmaf(xv.z, sW[(k4 * 4 + 2) * HID + lane], acc);
            acc = fmaf(xv.w, sW[(k4 * 4 + 3) * HID + lane], acc);
        }
        float di = g_dinv[n];
        g_bufA[(size_t)n * HID + lane] = acc;
        g_bufB[(size_t)n * HID + lane] = di * di * acc;
    }
}

// ============ edge scatter: agg[dst] += norm * hW[src] ============
// Each warp: loads 32 edges' indices coalesced, then processes 4 edges per
// inner step with 8 lanes/edge, float4 gather + red.global.v4.f32.add.
__global__ void k_scatter(const int* __restrict__ src,
                          const int* __restrict__ dst,
                          int E, int layer2) {
    float* to = layer2 ? g_bufC : g_bufB;
    int lane = threadIdx.x & 31;
    int sub  = lane >> 3;        // which of 4 edges this lane serves
    int q    = lane & 7;         // which float4 chunk of the 32 channels
    int wpb  = blockDim.x >> 5;
    long long warp_id = (long long)blockIdx.x * wpb + (threadIdx.x >> 5);
    long long nwarps  = (long long)gridDim.x * wpb;

    for (long long base = warp_id * 32; base < E; base += nwarps * 32) {
        long long e = base + lane;
        int s = 0, d = 0; float nrm = 0.0f;
        if (e < E) {
            s = __ldg(&src[e]);
            d = __ldg(&dst[e]);
            nrm = g_dinv[s] * g_dinv[d];
        }
        int cnt = (int)min((long long)32, (long long)E - base);
        #pragma unroll
        for (int j2 = 0; j2 < 8; j2++) {
            int ej = j2 * 4 + sub;                         // edge slot 0..31
            int   sj = __shfl_sync(0xffffffffu, s,   ej);
            int   dj = __shfl_sync(0xffffffffu, d,   ej);
            float nj = __shfl_sync(0xffffffffu, nrm, ej);
            if (ej < cnt) {
                float4 v = *(const float4*)(g_bufA + (size_t)sj * HID + q * 4);
                float* p = to + (size_t)dj * HID + q * 4;
                asm volatile("red.global.v4.f32.add [%0], {%1, %2, %3, %4};"
                             :: "l"(p),
                                "f"(v.x * nj), "f"(v.y * nj),
                                "f"(v.z * nj), "f"(v.w * nj)
                             : "memory");
            }
        }
    }
}

// ============ GEMM2: h = relu(agg1 + b1); hW2 = h @ W2 ; agg2 = dinv^2 * hW2 ============
__global__ void k_gemm2(const float* __restrict__ W2, const float* __restrict__ b1, int N) {
    __shared__ float sW[HID * HID];             // 4 KB
    __shared__ float sb[HID];
    for (int i = threadIdx.x; i < HID * HID; i += blockDim.x) sW[i] = W2[i];
    if (threadIdx.x < HID) sb[threadIdx.x] = b1[threadIdx.x];
    __syncthreads();

    int warp = threadIdx.x >> 5, lane = threadIdx.x & 31;
    for (int n = blockIdx.x * 8 + warp; n < N; n += gridDim.x * 8) {
        float hv = g_bufB[(size_t)n * HID + lane] + sb[lane];
        hv = fmaxf(hv, 0.0f);
        float acc = 0.0f;
        #pragma unroll
        for (int k = 0; k < HID; k++) {
            float hk = __shfl_sync(0xffffffffu, hv, k);
            acc = fmaf(hk, sW[k * HID + lane], acc);
        }
        float di = g_dinv[n];
        g_bufA[(size_t)n * HID + lane] = acc;   // hW2 (bufA reusable now)
        g_bufC[(size_t)n * HID + lane] = di * di * acc;
    }
}

// ============ head: scores[n+1] = relu(agg2 + b2) . Wh + bh ; scores[0] = cash ============
__global__ void k_score(const float* __restrict__ Wh, const float* __restrict__ b2,
                        const float* __restrict__ bh, const float* __restrict__ cash, int N) {
    int warp = threadIdx.x >> 5, lane = threadIdx.x & 31;
    int gwarp = blockIdx.x * (blockDim.x >> 5) + warp;
    if (gwarp == 0 && lane == 0) g_scores[0] = cash[0];
    float wh = Wh[lane], bb = b2[lane], bhv = bh[0];
    for (int n = gwarp; n < N; n += gridDim.x * (blockDim.x >> 5)) {
        float v = g_bufC[(size_t)n * HID + lane] + bb;
        v = fmaxf(v, 0.0f) * wh;
        #pragma unroll
        for (int o = 16; o > 0; o >>= 1) v += __shfl_xor_sync(0xffffffffu, v, o);
        if (lane == 0) g_scores[n + 1] = v + bhv;
    }
}

// ============ softmax ============
__device__ __forceinline__ void atomicMaxF(float* addr, float v) {
    if (v >= 0.0f) atomicMax((int*)addr, __float_as_int(v));
    else           atomicMin((unsigned int*)addr, __float_as_uint(v));
}

__global__ void k_max(int M) {
    float m = -INFINITY;
    for (int i = blockIdx.x * blockDim.x + threadIdx.x; i < M; i += gridDim.x * blockDim.x)
        m = fmaxf(m, g_scores[i]);
    #pragma unroll
    for (int o = 16; o > 0; o >>= 1) m = fmaxf(m, __shfl_xor_sync(0xffffffffu, m, o));
    __shared__ float sm[32];
    if ((threadIdx.x & 31) == 0) sm[threadIdx.x >> 5] = m;
    __syncthreads();
    if (threadIdx.x < 32) {
        float v = (threadIdx.x < (blockDim.x >> 5)) ? sm[threadIdx.x] : -INFINITY;
        #pragma unroll
        for (int o = 16; o > 0; o >>= 1) v = fmaxf(v, __shfl_xor_sync(0xffffffffu, v, o));
        if (threadIdx.x == 0) atomicMaxF(&g_max_v, v);
    }
}

__global__ void k_sumexp(int M) {
    float mx = g_max_v;
    float s = 0.0f;
    for (int i = blockIdx.x * blockDim.x + threadIdx.x; i < M; i += gridDim.x * blockDim.x)
        s += expf(g_scores[i] - mx);
    #pragma unroll
    for (int o = 16; o > 0; o >>= 1) s += __shfl_xor_sync(0xffffffffu, s, o);
    __shared__ float sm[32];
    if ((threadIdx.x & 31) == 0) sm[threadIdx.x >> 5] = s;
    __syncthreads();
    if (threadIdx.x < 32) {
        float v = (threadIdx.x < (blockDim.x >> 5)) ? sm[threadIdx.x] : 0.0f;
        #pragma unroll
        for (int o = 16; o > 0; o >>= 1) v += __shfl_xor_sync(0xffffffffu, v, o);
        if (threadIdx.x == 0) atomicAdd(&g_sum_v, v);
    }
}

__global__ void k_norm(float* __restrict__ out, int M) {
    float mx = g_max_v;
    float inv = 1.0f / g_sum_v;
    for (int i = blockIdx.x * blockDim.x + threadIdx.x; i < M; i += gridDim.x * blockDim.x)
        out[i] = expf(g_scores[i] - mx) * inv;
}

// ============ launch ============
extern "C" void kernel_launch(void* const* d_in, const int* in_sizes, int n_in,
                              void* d_out, int out_size) {
    const float* x    = (const float*)d_in[0];
    const int*   ei   = (const int*)d_in[1];     // JAX default x64-disabled -> int32
    const float* W1   = (const float*)d_in[2];
    const float* b1   = (const float*)d_in[3];
    const float* W2   = (const float*)d_in[4];
    const float* b2   = (const float*)d_in[5];
    const float* Wh   = (const float*)d_in[6];
    const float* bh   = (const float*)d_in[7];
    const float* cash = (const float*)d_in[8];
    float* out = (float*)d_out;

    int N = in_sizes[0] / IN_DIM;
    int E = in_sizes[1] / 2;
    const int* src = ei;
    const int* dst = ei + E;
    int M = N + 1;

    // degree + norm
    k_deg_init<<<(N + 255) / 256, 256>>>(N);
    k_deg_acc<<<(E + 255) / 256, 256>>>(dst, E);
    k_rsqrt<<<(N + 255) / 256, 256>>>(N);

    // layer 1
    k_gemm1<<<(N + 7) / 8, 256>>>(x, W1, N);
    k_scatter<<<4096, 256>>>(src, dst, E, 0);

    // layer 2
    k_gemm2<<<(N + 7) / 8, 256>>>(W2, b1, N);
    k_scatter<<<4096, 256>>>(src, dst, E, 1);

    // head + softmax
    k_score<<<(N + 7) / 8, 256>>>(Wh, b2, bh, cash, N);
    k_max<<<256, 256>>>(M);
    k_sumexp<<<256, 256>>>(M);
    k_norm<<<(M + 255) / 256, 256>>>(out, M);
}

// round 5
// speedup vs baseline: 1.7348x; 1.7348x over previous
#include <cuda_runtime.h>
#include <math.h>

#define N_MAX   100000
#define IN_DIM  128
#define HID     32
#define TILE    32

// ---- scratch (no allocation allowed), 16B-aligned for float4 access ----
__device__ __align__(16) float g_bufA[(size_t)N_MAX * HID];   // hW (layer1), then hW2 (layer2)
__device__ __align__(16) float g_bufB[(size_t)N_MAX * HID];   // agg1
__device__ __align__(16) float g_bufC[(size_t)N_MAX * HID];   // agg2
__device__ float g_dinv[N_MAX];                 // deg, then rsqrt(deg)
__device__ float g_scores[N_MAX + 1];
__device__ float g_max_v;
__device__ float g_sum_v;

// ============ degree ============
__global__ void k_deg_init(int N) {
    int i = blockIdx.x * blockDim.x + threadIdx.x;
    if (i < N) g_dinv[i] = 1.0f;               // self-loop
    if (i == 0) { g_max_v = -INFINITY; g_sum_v = 0.0f; }
}

__global__ void k_deg_acc(const int* __restrict__ dst, int E) {
    int i = blockIdx.x * blockDim.x + threadIdx.x;
    if (i < E) atomicAdd(&g_dinv[dst[i]], 1.0f);
}

__global__ void k_rsqrt(int N) {
    int i = blockIdx.x * blockDim.x + threadIdx.x;
    if (i < N) g_dinv[i] = rsqrtf(g_dinv[i]);
}

// ============ GEMM1 (tiled): hW = x @ W1 ; agg1 = dinv^2 * hW ============
// Block stages TILE=32 rows of x into smem (coalesced float4), then each of
// 8 warps computes 4 nodes x 32 channels, reusing each weight across 4 nodes.
__global__ __launch_bounds__(256) void k_gemm1(const float* __restrict__ x,
                                               const float* __restrict__ W1, int N) {
    __shared__ float sW[IN_DIM * HID];          // 16 KB
    __shared__ __align__(16) float sx[TILE * IN_DIM];  // 16 KB
    for (int i = threadIdx.x; i < IN_DIM * HID; i += blockDim.x) sW[i] = W1[i];

    int warp = threadIdx.x >> 5, lane = threadIdx.x & 31;

    for (int tile = blockIdx.x * TILE; tile < N; tile += gridDim.x * TILE) {
        __syncthreads();                        // protect sx reuse
        int rows = min(TILE, N - tile);
        // stage: rows * 32 float4, fully coalesced
        for (int i = threadIdx.x; i < rows * (IN_DIM / 4); i += blockDim.x) {
            int r = i >> 5, c = i & 31;
            ((float4*)sx)[r * 32 + c] =
                ((const float4*)(x + (size_t)(tile + r) * IN_DIM))[c];
        }
        __syncthreads();

        // each warp: 4 nodes, lane = output channel
        const float4* x0 = (const float4*)(sx + (warp * 4 + 0) * IN_DIM);
        const float4* x1 = (const float4*)(sx + (warp * 4 + 1) * IN_DIM);
        const float4* x2 = (const float4*)(sx + (warp * 4 + 2) * IN_DIM);
        const float4* x3 = (const float4*)(sx + (warp * 4 + 3) * IN_DIM);
        float acc0 = 0.f, acc1 = 0.f, acc2 = 0.f, acc3 = 0.f;
        #pragma unroll
        for (int k4 = 0; k4 < IN_DIM / 4; k4++) {
            float4 a = x0[k4], b = x1[k4], c = x2[k4], d = x3[k4];
            const float* wp = sW + k4 * 4 * HID + lane;
            float w0 = wp[0], w1 = wp[HID], w2 = wp[2 * HID], w3 = wp[3 * HID];
            acc0 = fmaf(a.x, w0, acc0); acc1 = fmaf(b.x, w0, acc1);
            acc2 = fmaf(c.x, w0, acc2); acc3 = fmaf(d.x, w0, acc3);
            acc0 = fmaf(a.y, w1, acc0); acc1 = fmaf(b.y, w1, acc1);
            acc2 = fmaf(c.y, w1, acc2); acc3 = fmaf(d.y, w1, acc3);
            acc0 = fmaf(a.z, w2, acc0); acc1 = fmaf(b.z, w2, acc1);
            acc2 = fmaf(c.z, w2, acc2); acc3 = fmaf(d.z, w2, acc3);
            acc0 = fmaf(a.w, w3, acc0); acc1 = fmaf(b.w, w3, acc1);
            acc2 = fmaf(c.w, w3, acc2); acc3 = fmaf(d.w, w3, acc3);
        }

        float accs[4] = {acc0, acc1, acc2, acc3};
        #pragma unroll
        for (int i = 0; i < 4; i++) {
            int n = tile + warp * 4 + i;
            if (n < N) {
                float di = g_dinv[n];
                g_bufA[(size_t)n * HID + lane] = accs[i];
                g_bufB[(size_t)n * HID + lane] = di * di * accs[i];
            }
        }
    }
}

// ============ edge scatter: agg[dst] += norm * hW[src] ============
// Each warp: loads 32 edges' indices coalesced, then processes 4 edges per
// inner step with 8 lanes/edge, float4 gather + red.global.v4.f32.add.
__global__ void k_scatter(const int* __restrict__ src,
                          const int* __restrict__ dst,
                          int E, int layer2) {
    float* to = layer2 ? g_bufC : g_bufB;
    int lane = threadIdx.x & 31;
    int sub  = lane >> 3;        // which of 4 edges this lane serves
    int q    = lane & 7;         // which float4 chunk of the 32 channels
    int wpb  = blockDim.x >> 5;
    long long warp_id = (long long)blockIdx.x * wpb + (threadIdx.x >> 5);
    long long nwarps  = (long long)gridDim.x * wpb;

    for (long long base = warp_id * 32; base < E; base += nwarps * 32) {
        long long e = base + lane;
        int s = 0, d = 0; float nrm = 0.0f;
        if (e < E) {
            s = __ldg(&src[e]);
            d = __ldg(&dst[e]);
            nrm = g_dinv[s] * g_dinv[d];
        }
        int cnt = (int)min((long long)32, (long long)E - base);
        #pragma unroll
        for (int j2 = 0; j2 < 8; j2++) {
            int ej = j2 * 4 + sub;                         // edge slot 0..31
            int   sj = __shfl_sync(0xffffffffu, s,   ej);
            int   dj = __shfl_sync(0xffffffffu, d,   ej);
            float nj = __shfl_sync(0xffffffffu, nrm, ej);
            if (ej < cnt) {
                float4 v = *(const float4*)(g_bufA + (size_t)sj * HID + q * 4);
                float* p = to + (size_t)dj * HID + q * 4;
                asm volatile("red.global.v4.f32.add [%0], {%1, %2, %3, %4};"
                             :: "l"(p),
                                "f"(v.x * nj), "f"(v.y * nj),
                                "f"(v.z * nj), "f"(v.w * nj)
                             : "memory");
            }
        }
    }
}

// ============ GEMM2: h = relu(agg1 + b1); hW2 = h @ W2 ; agg2 = dinv^2 * hW2 ============
__global__ void k_gemm2(const float* __restrict__ W2, const float* __restrict__ b1, int N) {
    __shared__ float sW[HID * HID];             // 4 KB
    __shared__ float sb[HID];
    for (int i = threadIdx.x; i < HID * HID; i += blockDim.x) sW[i] = W2[i];
    if (threadIdx.x < HID) sb[threadIdx.x] = b1[threadIdx.x];
    __syncthreads();

    int warp = threadIdx.x >> 5, lane = threadIdx.x & 31;
    for (int n = blockIdx.x * 8 + warp; n < N; n += gridDim.x * 8) {
        float hv = g_bufB[(size_t)n * HID + lane] + sb[lane];
        hv = fmaxf(hv, 0.0f);
        float acc = 0.0f;
        #pragma unroll
        for (int k = 0; k < HID; k++) {
            float hk = __shfl_sync(0xffffffffu, hv, k);
            acc = fmaf(hk, sW[k * HID + lane], acc);
        }
        float di = g_dinv[n];
        g_bufA[(size_t)n * HID + lane] = acc;   // hW2 (bufA reusable now)
        g_bufC[(size_t)n * HID + lane] = di * di * acc;
    }
}

// ============ head: scores[n+1] = relu(agg2 + b2) . Wh + bh ; scores[0] = cash ============
__global__ void k_score(const float* __restrict__ Wh, const float* __restrict__ b2,
                        const float* __restrict__ bh, const float* __restrict__ cash, int N) {
    int warp = threadIdx.x >> 5, lane = threadIdx.x & 31;
    int gwarp = blockIdx.x * (blockDim.x >> 5) + warp;
    if (gwarp == 0 && lane == 0) g_scores[0] = cash[0];
    float wh = Wh[lane], bb = b2[lane], bhv = bh[0];
    for (int n = gwarp; n < N; n += gridDim.x * (blockDim.x >> 5)) {
        float v = g_bufC[(size_t)n * HID + lane] + bb;
        v = fmaxf(v, 0.0f) * wh;
        #pragma unroll
        for (int o = 16; o > 0; o >>= 1) v += __shfl_xor_sync(0xffffffffu, v, o);
        if (lane == 0) g_scores[n + 1] = v + bhv;
    }
}

// ============ softmax ============
__device__ __forceinline__ void atomicMaxF(float* addr, float v) {
    if (v >= 0.0f) atomicMax((int*)addr, __float_as_int(v));
    else           atomicMin((unsigned int*)addr, __float_as_uint(v));
}

__global__ void k_max(int M) {
    float m = -INFINITY;
    for (int i = blockIdx.x * blockDim.x + threadIdx.x; i < M; i += gridDim.x * blockDim.x)
        m = fmaxf(m, g_scores[i]);
    #pragma unroll
    for (int o = 16; o > 0; o >>= 1) m = fmaxf(m, __shfl_xor_sync(0xffffffffu, m, o));
    __shared__ float sm[32];
    if ((threadIdx.x & 31) == 0) sm[threadIdx.x >> 5] = m;
    __syncthreads();
    if (threadIdx.x < 32) {
        float v = (threadIdx.x < (blockDim.x >> 5)) ? sm[threadIdx.x] : -INFINITY;
        #pragma unroll
        for (int o = 16; o > 0; o >>= 1) v = fmaxf(v, __shfl_xor_sync(0xffffffffu, v, o));
        if (threadIdx.x == 0) atomicMaxF(&g_max_v, v);
    }
}

__global__ void k_sumexp(int M) {
    float mx = g_max_v;
    float s = 0.0f;
    for (int i = blockIdx.x * blockDim.x + threadIdx.x; i < M; i += gridDim.x * blockDim.x)
        s += expf(g_scores[i] - mx);
    #pragma unroll
    for (int o = 16; o > 0; o >>= 1) s += __shfl_xor_sync(0xffffffffu, s, o);
    __shared__ float sm[32];
    if ((threadIdx.x & 31) == 0) sm[threadIdx.x >> 5] = s;
    __syncthreads();
    if (threadIdx.x < 32) {
        float v = (threadIdx.x < (blockDim.x >> 5)) ? sm[threadIdx.x] : 0.0f;
        #pragma unroll
        for (int o = 16; o > 0; o >>= 1) v += __shfl_xor_sync(0xffffffffu, v, o);
        if (threadIdx.x == 0) atomicAdd(&g_sum_v, v);
    }
}

__global__ void k_norm(float* __restrict__ out, int M) {
    float mx = g_max_v;
    float inv = 1.0f / g_sum_v;
    for (int i = blockIdx.x * blockDim.x + threadIdx.x; i < M; i += gridDim.x * blockDim.x)
        out[i] = expf(g_scores[i] - mx) * inv;
}

// ============ launch ============
extern "C" void kernel_launch(void* const* d_in, const int* in_sizes, int n_in,
                              void* d_out, int out_size) {
    const float* x    = (const float*)d_in[0];
    const int*   ei   = (const int*)d_in[1];     // int32 (JAX x64 disabled)
    const float* W1   = (const float*)d_in[2];
    const float* b1   = (const float*)d_in[3];
    const float* W2   = (const float*)d_in[4];
    const float* b2   = (const float*)d_in[5];
    const float* Wh   = (const float*)d_in[6];
    const float* bh   = (const float*)d_in[7];
    const float* cash = (const float*)d_in[8];
    float* out = (float*)d_out;

    int N = in_sizes[0] / IN_DIM;
    int E = in_sizes[1] / 2;
    const int* src = ei;
    const int* dst = ei + E;
    int M = N + 1;

    // degree + norm
    k_deg_init<<<(N + 255) / 256, 256>>>(N);
    k_deg_acc<<<(E + 255) / 256, 256>>>(dst, E);
    k_rsqrt<<<(N + 255) / 256, 256>>>(N);

    // layer 1
    k_gemm1<<<(N + TILE - 1) / TILE, 256>>>(x, W1, N);
    k_scatter<<<4096, 256>>>(src, dst, E, 0);

    // layer 2
    k_gemm2<<<(N + 7) / 8, 256>>>(W2, b1, N);
    k_scatter<<<4096, 256>>>(src, dst, E, 1);

    // head + softmax
    k_score<<<(N + 7) / 8, 256>>>(Wh, b2, bh, cash, N);
    k_max<<<256, 256>>>(M);
    k_sumexp<<<256, 256>>>(M);
    k_norm<<<(M + 255) / 256, 256>>>(out, M);
}

// round 7
// speedup vs baseline: 1.7472x; 1.0071x over previous
#include <cuda_runtime.h>
#include <math.h>

#define N_MAX   100000
#define E_MAX   3300000
#define IN_DIM  128
#define HID     32
#define TILE    64
#define FULL    0xffffffffu

// ---- scratch (no allocation allowed) ----
__device__ __align__(16) float g_bufA[(size_t)N_MAX * HID];   // hW1, then reused
__device__ __align__(16) float g_bufB[(size_t)N_MAX * HID];   // hW2
__device__ float g_dinv[N_MAX];
__device__ int   g_cnt[N_MAX];      // in-degree (no self loop)
__device__ int   g_base[N_MAX];     // bucket base
__device__ int   g_cur[N_MAX];      // fill cursor
__device__ int   g_esrc[E_MAX];     // bucketed src ids
__device__ float g_enorm[E_MAX];    // bucketed edge norms
__device__ int   g_total;
__device__ float g_scores[N_MAX + 1];
__device__ float g_max_v;
__device__ float g_sum_v;

// ============ init: zero counters, reset softmax state, scores[0]=cash ============
__global__ void k_init(const float* __restrict__ cash, int N) {
    int i = blockIdx.x * blockDim.x + threadIdx.x;
    if (i < N) g_cnt[i] = 0;
    if (i == 0) {
        g_total = 0;
        g_max_v = -INFINITY;
        g_sum_v = 0.0f;
        g_scores[0] = cash[0];
    }
}

// ============ count in-degree ============
__global__ void k_count(const int* __restrict__ dst, int E) {
    int i = blockIdx.x * blockDim.x + threadIdx.x;
    if (i < E) atomicAdd(&g_cnt[dst[i]], 1);
}

// ============ prep: dinv = rsqrt(deg), bucket bases via warp-scan ============
__global__ void k_prep(int N) {
    int i = blockIdx.x * blockDim.x + threadIdx.x;
    int lane = threadIdx.x & 31;
    int cnt = (i < N) ? g_cnt[i] : 0;
    if (i < N) g_dinv[i] = rsqrtf((float)(cnt + 1));   // +1 self-loop

    // warp inclusive scan of cnt
    int c = cnt;
    #pragma unroll
    for (int o = 1; o < 32; o <<= 1) {
        int t = __shfl_up_sync(FULL, c, o);
        if (lane >= o) c += t;
    }
    int warptot = __shfl_sync(FULL, c, 31);
    int excl = c - cnt;
    int wbase = 0;
    if (lane == 0) wbase = atomicAdd(&g_total, warptot);
    wbase = __shfl_sync(FULL, wbase, 0);
    if (i < N) {
        g_base[i] = wbase + excl;
        g_cur[i]  = wbase + excl;
    }
}

// ============ fill buckets: esrc + precomputed norm ============
__global__ void k_fill(const int* __restrict__ src, const int* __restrict__ dst, int E) {
    int i = blockIdx.x * blockDim.x + threadIdx.x;
    if (i < E) {
        int s = src[i], d = dst[i];
        float nrm = g_dinv[s] * g_dinv[d];
        int pos = atomicAdd(&g_cur[d], 1);
        g_esrc[pos]  = s;
        g_enorm[pos] = nrm;
    }
}

// ============ GEMM1 (tiled, 8 nodes/warp): bufA = x @ W1 ============
__global__ __launch_bounds__(256) void k_gemm1(const float* __restrict__ x,
                                               const float* __restrict__ W1, int N) {
    __shared__ float sW[IN_DIM * HID];                  // 16 KB
    __shared__ __align__(16) float sx[TILE * IN_DIM];   // 32 KB
    for (int i = threadIdx.x; i < IN_DIM * HID; i += blockDim.x) sW[i] = W1[i];

    int warp = threadIdx.x >> 5, lane = threadIdx.x & 31;

    for (int tile = blockIdx.x * TILE; tile < N; tile += gridDim.x * TILE) {
        __syncthreads();
        int rows = min(TILE, N - tile);
        for (int i = threadIdx.x; i < rows * (IN_DIM / 4); i += blockDim.x) {
            int r = i >> 5, c = i & 31;
            ((float4*)sx)[r * 32 + c] =
                ((const float4*)(x + (size_t)(tile + r) * IN_DIM))[c];
        }
        __syncthreads();

        const float4* xr = (const float4*)(sx + warp * 8 * IN_DIM);
        float acc[8] = {0.f, 0.f, 0.f, 0.f, 0.f, 0.f, 0.f, 0.f};
        #pragma unroll
        for (int k4 = 0; k4 < IN_DIM / 4; k4++) {
            const float* wp = sW + k4 * 4 * HID + lane;
            float w0 = wp[0], w1 = wp[HID], w2 = wp[2 * HID], w3 = wp[3 * HID];
            #pragma unroll
            for (int i = 0; i < 8; i++) {
                float4 a = xr[i * 32 + k4];     // broadcast within warp
                acc[i] = fmaf(a.x, w0, acc[i]);
                acc[i] = fmaf(a.y, w1, acc[i]);
                acc[i] = fmaf(a.z, w2, acc[i]);
                acc[i] = fmaf(a.w, w3, acc[i]);
            }
        }
        #pragma unroll
        for (int i = 0; i < 8; i++) {
            int n = tile + warp * 8 + i;
            if (n < N) g_bufA[(size_t)n * HID + lane] = acc[i];
        }
    }
}

// ============ gather core: acc = dinv^2*from[d] + sum_e norm_e * from[src_e] ============
__device__ __forceinline__ float gather_row(const float* __restrict__ from,
                                            int d, int lane) {
    int base = g_base[d], cnt = g_cnt[d];
    float dd = g_dinv[d];
    float acc = dd * dd * from[(size_t)d * HID + lane];
    for (int j0 = 0; j0 < cnt; j0 += 32) {
        int jn = min(32, cnt - j0);
        int s = 0; float nm = 0.0f;
        if (lane < jn) {
            s  = g_esrc[base + j0 + lane];
            nm = g_enorm[base + j0 + lane];
        }
        int j = 0;
        for (; j + 4 <= jn; j += 4) {
            int   s0 = __shfl_sync(FULL, s,  j);
            int   s1 = __shfl_sync(FULL, s,  j + 1);
            int   s2 = __shfl_sync(FULL, s,  j + 2);
            int   s3 = __shfl_sync(FULL, s,  j + 3);
            float n0 = __shfl_sync(FULL, nm, j);
            float n1 = __shfl_sync(FULL, nm, j + 1);
            float n2 = __shfl_sync(FULL, nm, j + 2);
            float n3 = __shfl_sync(FULL, nm, j + 3);
            float v0 = from[(size_t)s0 * HID + lane];
            float v1 = from[(size_t)s1 * HID + lane];
            float v2 = from[(size_t)s2 * HID + lane];
            float v3 = from[(size_t)s3 * HID + lane];
            acc = fmaf(n0, v0, acc);
            acc = fmaf(n1, v1, acc);
            acc = fmaf(n2, v2, acc);
            acc = fmaf(n3, v3, acc);
        }
        for (; j < jn; j++) {
            int   sj = __shfl_sync(FULL, s,  j);
            float nj = __shfl_sync(FULL, nm, j);
            acc = fmaf(nj, from[(size_t)sj * HID + lane], acc);
        }
    }
    return acc;
}

// ============ gather1 + fused gemm2: bufB = relu(agg1+b1) @ W2 ============
__global__ void k_gather1(const float* __restrict__ W2, const float* __restrict__ b1, int N) {
    __shared__ float sW[HID * HID];
    for (int i = threadIdx.x; i < HID * HID; i += blockDim.x) sW[i] = W2[i];
    __syncthreads();

    int lane = threadIdx.x & 31;
    int gwarp = blockIdx.x * (blockDim.x >> 5) + (threadIdx.x >> 5);
    int nw = gridDim.x * (blockDim.x >> 5);
    float bb = b1[lane];

    for (int d = gwarp; d < N; d += nw) {
        float acc = gather_row(g_bufA, d, lane);
        float h = fmaxf(acc + bb, 0.0f);
        float o = 0.0f;
        #pragma unroll
        for (int k = 0; k < HID; k++) {
            float hk = __shfl_sync(FULL, h, k);
            o = fmaf(hk, sW[k * HID + lane], o);
        }
        g_bufB[(size_t)d * HID + lane] = o;
    }
}

// ============ gather2 + fused head: scores[d+1] = relu(agg2+b2).Wh + bh ============
__global__ void k_gather2(const float* __restrict__ Wh, const float* __restrict__ b2,
                          const float* __restrict__ bh, int N) {
    int lane = threadIdx.x & 31;
    int gwarp = blockIdx.x * (blockDim.x >> 5) + (threadIdx.x >> 5);
    int nw = gridDim.x * (blockDim.x >> 5);
    float bb = b2[lane], wh = Wh[lane], bhv = bh[0];

    for (int d = gwarp; d < N; d += nw) {
        float acc = gather_row(g_bufB, d, lane);
        float v = fmaxf(acc + bb, 0.0f) * wh;
        #pragma unroll
        for (int o = 16; o > 0; o >>= 1) v += __shfl_xor_sync(FULL, v, o);
        if (lane == 0) g_scores[d + 1] = v + bhv;
    }
}

// ============ softmax ============
__device__ __forceinline__ void atomicMaxF(float* addr, float v) {
    if (v >= 0.0f) atomicMax((int*)addr, __float_as_int(v));
    else           atomicMin((unsigned int*)addr, __float_as_uint(v));
}

__global__ void k_max(int M) {
    float m = -INFINITY;
    for (int i = blockIdx.x * blockDim.x + threadIdx.x; i < M; i += gridDim.x * blockDim.x)
        m = fmaxf(m, g_scores[i]);
    #pragma unroll
    for (int o = 16; o > 0; o >>= 1) m = fmaxf(m, __shfl_xor_sync(FULL, m, o));
    __shared__ float sm[32];
    if ((threadIdx.x & 31) == 0) sm[threadIdx.x >> 5] = m;
    __syncthreads();
    if (threadIdx.x < 32) {
        float v = (threadIdx.x < (blockDim.x >> 5)) ? sm[threadIdx.x] : -INFINITY;
        #pragma unroll
        for (int o = 16; o > 0; o >>= 1) v = fmaxf(v, __shfl_xor_sync(FULL, v, o));
        if (threadIdx.x == 0) atomicMaxF(&g_max_v, v);
    }
}

__global__ void k_sumexp(int M) {
    float mx = g_max_v;
    float s = 0.0f;
    for (int i = blockIdx.x * blockDim.x + threadIdx.x; i < M; i += gridDim.x * blockDim.x)
        s += expf(g_scores[i] - mx);
    #pragma unroll
    for (int o = 16; o > 0; o >>= 1) s += __shfl_xor_sync(FULL, s, o);
    __shared__ float sm[32];
    if ((threadIdx.x & 31) == 0) sm[threadIdx.x >> 5] = s;
    __syncthreads();
    if (threadIdx.x < 32) {
        float v = (threadIdx.x < (blockDim.x >> 5)) ? sm[threadIdx.x] : 0.0f;
        #pragma unroll
        for (int o = 16; o > 0; o >>= 1) v += __shfl_xor_sync(FULL, v, o);
        if (threadIdx.x == 0) atomicAdd(&g_sum_v, v);
    }
}

__global__ void k_norm(float* __restrict__ out, int M) {
    float mx = g_max_v;
    float inv = 1.0f / g_sum_v;
    for (int i = blockIdx.x * blockDim.x + threadIdx.x; i < M; i += gridDim.x * blockDim.x)
        out[i] = expf(g_scores[i] - mx) * inv;
}

// ============ launch ============
extern "C" void kernel_launch(void* const* d_in, const int* in_sizes, int n_in,
                              void* d_out, int out_size) {
    const float* x    = (const float*)d_in[0];
    const int*   ei   = (const int*)d_in[1];     // int32 (JAX x64 disabled)
    const float* W1   = (const float*)d_in[2];
    const float* b1   = (const float*)d_in[3];
    const float* W2   = (const float*)d_in[4];
    const float* b2   = (const float*)d_in[5];
    const float* Wh   = (const float*)d_in[6];
    const float* bh   = (const float*)d_in[7];
    const float* cash = (const float*)d_in[8];
    float* out = (float*)d_out;

    int N = in_sizes[0] / IN_DIM;
    int E = in_sizes[1] / 2;
    const int* src = ei;
    const int* dst = ei + E;
    int M = N + 1;

    // CSR bucket build (reused by both layers)
    k_init<<<(N + 255) / 256, 256>>>(cash, N);
    k_count<<<(E + 255) / 256, 256>>>(dst, E);
    k_prep<<<(N + 255) / 256, 256>>>(N);
    k_fill<<<(E + 255) / 256, 256>>>(src, dst, E);

    // dense transform (overlaps nothing; bufA independent of buckets)
    k_gemm1<<<(N + TILE - 1) / TILE, 256>>>(x, W1, N);

    // layer 1 propagate + fused gemm2
    k_gather1<<<(N + 7) / 8, 256>>>(W2, b1, N);
    // layer 2 propagate + fused head
    k_gather2<<<(N + 7) / 8, 256>>>(Wh, b2, bh, N);

    // softmax
    k_max<<<256, 256>>>(M);
    k_sumexp<<<256, 256>>>(M);
    k_norm<<<(M + 255) / 256, 256>>>(out, M);
}

// round 8
// speedup vs baseline: 2.0885x; 1.1953x over previous
#include <cuda_runtime.h>
#include <math.h>

#define N_MAX   100000
#define E_MAX   3300000
#define IN_DIM  128
#define HID     32
#define TILE    64
#define FULL    0xffffffffu

// ---- scratch (no allocation allowed) ----
__device__ __align__(16) float g_bufA[(size_t)N_MAX * HID];   // dinv * (x@W1)
__device__ __align__(16) float g_bufB[(size_t)N_MAX * HID];   // dinv * (h@W2)
__device__ float g_dinv[N_MAX];
__device__ int   g_cnt[N_MAX];      // in-degree (no self loop)
__device__ int   g_base[N_MAX];     // bucket base
__device__ int   g_cur[N_MAX];      // fill cursor
__device__ int   g_esrc[E_MAX];     // bucketed src ids
__device__ int   g_total;
__device__ float g_scores[N_MAX + 1];
__device__ float g_max_v;
__device__ float g_sum_v;

// ============ init: zero counters, reset softmax state, scores[0]=cash ============
__global__ void k_init(const float* __restrict__ cash, int N) {
    int i = blockIdx.x * blockDim.x + threadIdx.x;
    if (i < N) g_cnt[i] = 0;
    if (i == 0) {
        g_total = 0;
        g_max_v = -INFINITY;
        g_sum_v = 0.0f;
        g_scores[0] = cash[0];
    }
}

// ============ count in-degree ============
__global__ void k_count(const int* __restrict__ dst, int E) {
    int i = blockIdx.x * blockDim.x + threadIdx.x;
    if (i < E) atomicAdd(&g_cnt[dst[i]], 1);
}

// ============ prep: dinv = rsqrt(deg), bucket bases via warp-scan ============
__global__ void k_prep(int N) {
    int i = blockIdx.x * blockDim.x + threadIdx.x;
    int lane = threadIdx.x & 31;
    int cnt = (i < N) ? g_cnt[i] : 0;
    if (i < N) g_dinv[i] = rsqrtf((float)(cnt + 1));   // +1 self-loop

    // warp inclusive scan of cnt
    int c = cnt;
    #pragma unroll
    for (int o = 1; o < 32; o <<= 1) {
        int t = __shfl_up_sync(FULL, c, o);
        if (lane >= o) c += t;
    }
    int warptot = __shfl_sync(FULL, c, 31);
    int excl = c - cnt;
    int wbase = 0;
    if (lane == 0) wbase = atomicAdd(&g_total, warptot);
    wbase = __shfl_sync(FULL, wbase, 0);
    if (i < N) {
        g_base[i] = wbase + excl;
        g_cur[i]  = wbase + excl;
    }
}

// ============ fill buckets: src id only (norm factored out) ============
__global__ void k_fill(const int* __restrict__ src, const int* __restrict__ dst, int E) {
    int i = blockIdx.x * blockDim.x + threadIdx.x;
    if (i < E) {
        int s = src[i], d = dst[i];
        int pos = atomicAdd(&g_cur[d], 1);
        g_esrc[pos] = s;
    }
}

// ============ GEMM1 (tiled, 8 nodes/warp): bufA = dinv * (x @ W1) ============
__global__ __launch_bounds__(256) void k_gemm1(const float* __restrict__ x,
                                               const float* __restrict__ W1, int N) {
    __shared__ float sW[IN_DIM * HID];                  // 16 KB
    __shared__ __align__(16) float sx[TILE * IN_DIM];   // 32 KB
    for (int i = threadIdx.x; i < IN_DIM * HID; i += blockDim.x) sW[i] = W1[i];

    int warp = threadIdx.x >> 5, lane = threadIdx.x & 31;

    for (int tile = blockIdx.x * TILE; tile < N; tile += gridDim.x * TILE) {
        __syncthreads();
        int rows = min(TILE, N - tile);
        for (int i = threadIdx.x; i < rows * (IN_DIM / 4); i += blockDim.x) {
            int r = i >> 5, c = i & 31;
            ((float4*)sx)[r * 32 + c] =
                ((const float4*)(x + (size_t)(tile + r) * IN_DIM))[c];
        }
        __syncthreads();

        const float4* xr = (const float4*)(sx + warp * 8 * IN_DIM);
        float acc[8] = {0.f, 0.f, 0.f, 0.f, 0.f, 0.f, 0.f, 0.f};
        #pragma unroll
        for (int k4 = 0; k4 < IN_DIM / 4; k4++) {
            const float* wp = sW + k4 * 4 * HID + lane;
            float w0 = wp[0], w1 = wp[HID], w2 = wp[2 * HID], w3 = wp[3 * HID];
            #pragma unroll
            for (int i = 0; i < 8; i++) {
                float4 a = xr[i * 32 + k4];     // broadcast within warp
                acc[i] = fmaf(a.x, w0, acc[i]);
                acc[i] = fmaf(a.y, w1, acc[i]);
                acc[i] = fmaf(a.z, w2, acc[i]);
                acc[i] = fmaf(a.w, w3, acc[i]);
            }
        }
        #pragma unroll
        for (int i = 0; i < 8; i++) {
            int n = tile + warp * 8 + i;
            if (n < N) g_bufA[(size_t)n * HID + lane] = g_dinv[n] * acc[i];
        }
    }
}

// ============ gather core: returns bufX[d] + sum_e bufX[src_e]  (per-lane channel) ============
__device__ __forceinline__ float gather_row(const float* __restrict__ from,
                                            int d, int lane) {
    int base = g_base[d], cnt = g_cnt[d];
    float acc = from[(size_t)d * HID + lane];
    for (int j0 = 0; j0 < cnt; j0 += 32) {
        int jn = min(32, cnt - j0);
        int s = 0;
        if (lane < jn) s = g_esrc[base + j0 + lane];
        int j = 0;
        for (; j + 4 <= jn; j += 4) {
            int s0 = __shfl_sync(FULL, s, j);
            int s1 = __shfl_sync(FULL, s, j + 1);
            int s2 = __shfl_sync(FULL, s, j + 2);
            int s3 = __shfl_sync(FULL, s, j + 3);
            float v0 = from[(size_t)s0 * HID + lane];
            float v1 = from[(size_t)s1 * HID + lane];
            float v2 = from[(size_t)s2 * HID + lane];
            float v3 = from[(size_t)s3 * HID + lane];
            acc += v0 + v1 + v2 + v3;
        }
        for (; j < jn; j++) {
            int sj = __shfl_sync(FULL, s, j);
            acc += from[(size_t)sj * HID + lane];
        }
    }
    return acc;
}

// ============ gather1 + fused gemm2: bufB = dinv * (relu(dinv*sum + b1) @ W2) ============
__global__ void k_gather1(const float* __restrict__ W2, const float* __restrict__ b1, int N) {
    __shared__ float sW[HID * HID];
    for (int i = threadIdx.x; i < HID * HID; i += blockDim.x) sW[i] = W2[i];
    __syncthreads();

    int lane = threadIdx.x & 31;
    int gwarp = blockIdx.x * (blockDim.x >> 5) + (threadIdx.x >> 5);
    int nw = gridDim.x * (blockDim.x >> 5);
    float bb = b1[lane];

    for (int d = gwarp; d < N; d += nw) {
        float t = gather_row(g_bufA, d, lane);
        float dd = g_dinv[d];
        float h = fmaxf(fmaf(dd, t, bb), 0.0f);
        float o = 0.0f;
        #pragma unroll
        for (int k = 0; k < HID; k++) {
            float hk = __shfl_sync(FULL, h, k);
            o = fmaf(hk, sW[k * HID + lane], o);
        }
        g_bufB[(size_t)d * HID + lane] = dd * o;
    }
}

// ============ gather2 + fused head: scores[d+1] = relu(dinv*sum+b2).Wh + bh ============
__global__ void k_gather2(const float* __restrict__ Wh, const float* __restrict__ b2,
                          const float* __restrict__ bh, int N) {
    int lane = threadIdx.x & 31;
    int gwarp = blockIdx.x * (blockDim.x >> 5) + (threadIdx.x >> 5);
    int nw = gridDim.x * (blockDim.x >> 5);
    float bb = b2[lane], wh = Wh[lane], bhv = bh[0];

    for (int d = gwarp; d < N; d += nw) {
        float t = gather_row(g_bufB, d, lane);
        float dd = g_dinv[d];
        float v = fmaxf(fmaf(dd, t, bb), 0.0f) * wh;
        #pragma unroll
        for (int o = 16; o > 0; o >>= 1) v += __shfl_xor_sync(FULL, v, o);
        if (lane == 0) g_scores[d + 1] = v + bhv;
    }
}

// ============ softmax ============
__device__ __forceinline__ void atomicMaxF(float* addr, float v) {
    if (v >= 0.0f) atomicMax((int*)addr, __float_as_int(v));
    else           atomicMin((unsigned int*)addr, __float_as_uint(v));
}

__global__ void k_max(int M) {
    float m = -INFINITY;
    for (int i = blockIdx.x * blockDim.x + threadIdx.x; i < M; i += gridDim.x * blockDim.x)
        m = fmaxf(m, g_scores[i]);
    #pragma unroll
    for (int o = 16; o > 0; o >>= 1) m = fmaxf(m, __shfl_xor_sync(FULL, m, o));
    __shared__ float sm[32];
    if ((threadIdx.x & 31) == 0) sm[threadIdx.x >> 5] = m;
    __syncthreads();
    if (threadIdx.x < 32) {
        float v = (threadIdx.x < (blockDim.x >> 5)) ? sm[threadIdx.x] : -INFINITY;
        #pragma unroll
        for (int o = 16; o > 0; o >>= 1) v = fmaxf(v, __shfl_xor_sync(FULL, v, o));
        if (threadIdx.x == 0) atomicMaxF(&g_max_v, v);
    }
}

__global__ void k_sumexp(int M) {
    float mx = g_max_v;
    float s = 0.0f;
    for (int i = blockIdx.x * blockDim.x + threadIdx.x; i < M; i += gridDim.x * blockDim.x)
        s += expf(g_scores[i] - mx);
    #pragma unroll
    for (int o = 16; o > 0; o >>= 1) s += __shfl_xor_sync(FULL, s, o);
    __shared__ float sm[32];
    if ((threadIdx.x & 31) == 0) sm[threadIdx.x >> 5] = s;
    __syncthreads();
    if (threadIdx.x < 32) {
        float v = (threadIdx.x < (blockDim.x >> 5)) ? sm[threadIdx.x] : 0.0f;
        #pragma unroll
        for (int o = 16; o > 0; o >>= 1) v += __shfl_xor_sync(FULL, v, o);
        if (threadIdx.x == 0) atomicAdd(&g_sum_v, v);
    }
}

__global__ void k_norm(float* __restrict__ out, int M) {
    float mx = g_max_v;
    float inv = 1.0f / g_sum_v;
    for (int i = blockIdx.x * blockDim.x + threadIdx.x; i < M; i += gridDim.x * blockDim.x)
        out[i] = expf(g_scores[i] - mx) * inv;
}

// ============ launch ============
extern "C" void kernel_launch(void* const* d_in, const int* in_sizes, int n_in,
                              void* d_out, int out_size) {
    const float* x    = (const float*)d_in[0];
    const int*   ei   = (const int*)d_in[1];     // int32 (JAX x64 disabled)
    const float* W1   = (const float*)d_in[2];
    const float* b1   = (const float*)d_in[3];
    const float* W2   = (const float*)d_in[4];
    const float* b2   = (const float*)d_in[5];
    const float* Wh   = (const float*)d_in[6];
    const float* bh   = (const float*)d_in[7];
    const float* cash = (const float*)d_in[8];
    float* out = (float*)d_out;

    int N = in_sizes[0] / IN_DIM;
    int E = in_sizes[1] / 2;
    const int* src = ei;
    const int* dst = ei + E;
    int M = N + 1;

    // CSR bucket build (reused by both layers)
    k_init<<<(N + 255) / 256, 256>>>(cash, N);
    k_count<<<(E + 255) / 256, 256>>>(dst, E);
    k_prep<<<(N + 255) / 256, 256>>>(N);
    k_fill<<<(E + 255) / 256, 256>>>(src, dst, E);

    // dense transform (needs dinv from prep)
    k_gemm1<<<(N + TILE - 1) / TILE, 256>>>(x, W1, N);

    // layer 1 propagate + fused gemm2
    k_gather1<<<(N + 7) / 8, 256>>>(W2, b1, N);
    // layer 2 propagate + fused head
    k_gather2<<<(N + 7) / 8, 256>>>(Wh, b2, bh, N);

    // softmax
    k_max<<<256, 256>>>(M);
    k_sumexp<<<256, 256>>>(M);
    k_norm<<<(M + 255) / 256, 256>>>(out, M);
}

// round 9
// speedup vs baseline: 2.1499x; 1.0294x over previous
#include <cuda_runtime.h>
#include <math.h>

#define N_MAX   100000
#define E_MAX   3300000
#define IN_DIM  128
#define HID     32
#define TILE    64
#define FULL    0xffffffffu

// ---- scratch (no allocation allowed) ----
__device__ __align__(16) float g_bufA[(size_t)N_MAX * HID];   // dinv * (x@W1)
__device__ __align__(16) float g_bufB[(size_t)N_MAX * HID];   // dinv * (h@W2)
__device__ float g_dinv[N_MAX];
__device__ int   g_cnt[N_MAX];      // in-degree (no self loop)
__device__ int   g_base[N_MAX];     // bucket base
__device__ int   g_esrc[E_MAX];     // bucketed src ids
__device__ int   g_eoff[E_MAX];     // per-edge offset within its dst bucket
__device__ int   g_total;
__device__ float g_scores[N_MAX + 1];
__device__ float g_max_v;
__device__ float g_sum_v;

// ============ init: zero counters, reset softmax state, scores[0]=cash ============
__global__ void k_init(const float* __restrict__ cash, int N) {
    int i = blockIdx.x * blockDim.x + threadIdx.x;
    if (i < N) g_cnt[i] = 0;
    if (i == 0) {
        g_total = 0;
        g_max_v = -INFINITY;
        g_sum_v = 0.0f;
        g_scores[0] = cash[0];
    }
}

// ============ count in-degree, record within-bucket offset (coalesced) ============
__global__ void k_count(const int* __restrict__ dst, int E) {
    int i = blockIdx.x * blockDim.x + threadIdx.x;
    if (i < E) g_eoff[i] = atomicAdd(&g_cnt[dst[i]], 1);
}

// ============ prep: dinv = rsqrt(deg), bucket bases via warp-scan ============
__global__ void k_prep(int N) {
    int i = blockIdx.x * blockDim.x + threadIdx.x;
    int lane = threadIdx.x & 31;
    int cnt = (i < N) ? g_cnt[i] : 0;
    if (i < N) g_dinv[i] = rsqrtf((float)(cnt + 1));   // +1 self-loop

    // warp inclusive scan of cnt
    int c = cnt;
    #pragma unroll
    for (int o = 1; o < 32; o <<= 1) {
        int t = __shfl_up_sync(FULL, c, o);
        if (lane >= o) c += t;
    }
    int warptot = __shfl_sync(FULL, c, 31);
    int excl = c - cnt;
    int wbase = 0;
    if (lane == 0) wbase = atomicAdd(&g_total, warptot);
    wbase = __shfl_sync(FULL, wbase, 0);
    if (i < N) g_base[i] = wbase + excl;
}

// ============ fill buckets: atomic-free scatter of src ids ============
__global__ void k_fill(const int* __restrict__ src, const int* __restrict__ dst, int E) {
    int i = blockIdx.x * blockDim.x + threadIdx.x;
    if (i < E) {
        int d = dst[i];
        int pos = g_base[d] + g_eoff[i];
        g_esrc[pos] = src[i];
    }
}

// ============ GEMM1 (tiled, 8 nodes/warp): bufA = dinv * (x @ W1) ============
__global__ __launch_bounds__(256) void k_gemm1(const float* __restrict__ x,
                                               const float* __restrict__ W1, int N) {
    __shared__ float sW[IN_DIM * HID];                  // 16 KB
    __shared__ __align__(16) float sx[TILE * IN_DIM];   // 32 KB
    for (int i = threadIdx.x; i < IN_DIM * HID; i += blockDim.x) sW[i] = W1[i];

    int warp = threadIdx.x >> 5, lane = threadIdx.x & 31;

    for (int tile = blockIdx.x * TILE; tile < N; tile += gridDim.x * TILE) {
        __syncthreads();
        int rows = min(TILE, N - tile);
        for (int i = threadIdx.x; i < rows * (IN_DIM / 4); i += blockDim.x) {
            int r = i >> 5, c = i & 31;
            ((float4*)sx)[r * 32 + c] =
                ((const float4*)(x + (size_t)(tile + r) * IN_DIM))[c];
        }
        __syncthreads();

        const float4* xr = (const float4*)(sx + warp * 8 * IN_DIM);
        float acc[8] = {0.f, 0.f, 0.f, 0.f, 0.f, 0.f, 0.f, 0.f};
        #pragma unroll
        for (int k4 = 0; k4 < IN_DIM / 4; k4++) {
            const float* wp = sW + k4 * 4 * HID + lane;
            float w0 = wp[0], w1 = wp[HID], w2 = wp[2 * HID], w3 = wp[3 * HID];
            #pragma unroll
            for (int i = 0; i < 8; i++) {
                float4 a = xr[i * 32 + k4];     // broadcast within warp
                acc[i] = fmaf(a.x, w0, acc[i]);
                acc[i] = fmaf(a.y, w1, acc[i]);
                acc[i] = fmaf(a.z, w2, acc[i]);
                acc[i] = fmaf(a.w, w3, acc[i]);
            }
        }
        #pragma unroll
        for (int i = 0; i < 8; i++) {
            int n = tile + warp * 8 + i;
            if (n < N) g_bufA[(size_t)n * HID + lane] = g_dinv[n] * acc[i];
        }
    }
}

// ============ gather core: returns bufX[d] + sum_e bufX[src_e]  (per-lane channel) ============
__device__ __forceinline__ float gather_row(const float* __restrict__ from,
                                            int d, int lane) {
    int base = g_base[d], cnt = g_cnt[d];
    float acc = from[(size_t)d * HID + lane];
    for (int j0 = 0; j0 < cnt; j0 += 32) {
        int jn = min(32, cnt - j0);
        int s = 0;
        if (lane < jn) s = g_esrc[base + j0 + lane];
        int j = 0;
        for (; j + 8 <= jn; j += 8) {
            int s0 = __shfl_sync(FULL, s, j);
            int s1 = __shfl_sync(FULL, s, j + 1);
            int s2 = __shfl_sync(FULL, s, j + 2);
            int s3 = __shfl_sync(FULL, s, j + 3);
            int s4 = __shfl_sync(FULL, s, j + 4);
            int s5 = __shfl_sync(FULL, s, j + 5);
            int s6 = __shfl_sync(FULL, s, j + 6);
            int s7 = __shfl_sync(FULL, s, j + 7);
            float v0 = from[(size_t)s0 * HID + lane];
            float v1 = from[(size_t)s1 * HID + lane];
            float v2 = from[(size_t)s2 * HID + lane];
            float v3 = from[(size_t)s3 * HID + lane];
            float v4 = from[(size_t)s4 * HID + lane];
            float v5 = from[(size_t)s5 * HID + lane];
            float v6 = from[(size_t)s6 * HID + lane];
            float v7 = from[(size_t)s7 * HID + lane];
            acc += ((v0 + v1) + (v2 + v3)) + ((v4 + v5) + (v6 + v7));
        }
        for (; j < jn; j++) {
            int sj = __shfl_sync(FULL, s, j);
            acc += from[(size_t)sj * HID + lane];
        }
    }
    return acc;
}

// ============ gather1 + fused gemm2: bufB = dinv * (relu(dinv*sum + b1) @ W2) ============
__global__ void k_gather1(const float* __restrict__ W2, const float* __restrict__ b1, int N) {
    __shared__ float sW[HID * HID];
    for (int i = threadIdx.x; i < HID * HID; i += blockDim.x) sW[i] = W2[i];
    __syncthreads();

    int lane = threadIdx.x & 31;
    int gwarp = blockIdx.x * (blockDim.x >> 5) + (threadIdx.x >> 5);
    int nw = gridDim.x * (blockDim.x >> 5);
    float bb = b1[lane];

    for (int d = gwarp; d < N; d += nw) {
        float t = gather_row(g_bufA, d, lane);
        float dd = g_dinv[d];
        float h = fmaxf(fmaf(dd, t, bb), 0.0f);
        float o = 0.0f;
        #pragma unroll
        for (int k = 0; k < HID; k++) {
            float hk = __shfl_sync(FULL, h, k);
            o = fmaf(hk, sW[k * HID + lane], o);
        }
        g_bufB[(size_t)d * HID + lane] = dd * o;
    }
}

// ============ gather2 + fused head: scores[d+1] = relu(dinv*sum+b2).Wh + bh ============
__global__ void k_gather2(const float* __restrict__ Wh, const float* __restrict__ b2,
                          const float* __restrict__ bh, int N) {
    int lane = threadIdx.x & 31;
    int gwarp = blockIdx.x * (blockDim.x >> 5) + (threadIdx.x >> 5);
    int nw = gridDim.x * (blockDim.x >> 5);
    float bb = b2[lane], wh = Wh[lane], bhv = bh[0];

    for (int d = gwarp; d < N; d += nw) {
        float t = gather_row(g_bufB, d, lane);
        float dd = g_dinv[d];
        float v = fmaxf(fmaf(dd, t, bb), 0.0f) * wh;
        #pragma unroll
        for (int o = 16; o > 0; o >>= 1) v += __shfl_xor_sync(FULL, v, o);
        if (lane == 0) g_scores[d + 1] = v + bhv;
    }
}

// ============ softmax ============
__device__ __forceinline__ void atomicMaxF(float* addr, float v) {
    if (v >= 0.0f) atomicMax((int*)addr, __float_as_int(v));
    else           atomicMin((unsigned int*)addr, __float_as_uint(v));
}

__global__ void k_max(int M) {
    float m = -INFINITY;
    for (int i = blockIdx.x * blockDim.x + threadIdx.x; i < M; i += gridDim.x * blockDim.x)
        m = fmaxf(m, g_scores[i]);
    #pragma unroll
    for (int o = 16; o > 0; o >>= 1) m = fmaxf(m, __shfl_xor_sync(FULL, m, o));
    __shared__ float sm[32];
    if ((threadIdx.x & 31) == 0) sm[threadIdx.x >> 5] = m;
    __syncthreads();
    if (threadIdx.x < 32) {
        float v = (threadIdx.x < (blockDim.x >> 5)) ? sm[threadIdx.x] : -INFINITY;
        #pragma unroll
        for (int o = 16; o > 0; o >>= 1) v = fmaxf(v, __shfl_xor_sync(FULL, v, o));
        if (threadIdx.x == 0) atomicMaxF(&g_max_v, v);
    }
}

__global__ void k_sumexp(int M) {
    float mx = g_max_v;
    float s = 0.0f;
    for (int i = blockIdx.x * blockDim.x + threadIdx.x; i < M; i += gridDim.x * blockDim.x)
        s += expf(g_scores[i] - mx);
    #pragma unroll
    for (int o = 16; o > 0; o >>= 1) s += __shfl_xor_sync(FULL, s, o);
    __shared__ float sm[32];
    if ((threadIdx.x & 31) == 0) sm[threadIdx.x >> 5] = s;
    __syncthreads();
    if (threadIdx.x < 32) {
        float v = (threadIdx.x < (blockDim.x >> 5)) ? sm[threadIdx.x] : 0.0f;
        #pragma unroll
        for (int o = 16; o > 0; o >>= 1) v += __shfl_xor_sync(FULL, v, o);
        if (threadIdx.x == 0) atomicAdd(&g_sum_v, v);
    }
}

__global__ void k_norm(float* __restrict__ out, int M) {
    float mx = g_max_v;
    float inv = 1.0f / g_sum_v;
    for (int i = blockIdx.x * blockDim.x + threadIdx.x; i < M; i += gridDim.x * blockDim.x)
        out[i] = expf(g_scores[i] - mx) * inv;
}

// ============ launch ============
extern "C" void kernel_launch(void* const* d_in, const int* in_sizes, int n_in,
                              void* d_out, int out_size) {
    const float* x    = (const float*)d_in[0];
    const int*   ei   = (const int*)d_in[1];     // int32 (JAX x64 disabled)
    const float* W1   = (const float*)d_in[2];
    const float* b1   = (const float*)d_in[3];
    const float* W2   = (const float*)d_in[4];
    const float* b2   = (const float*)d_in[5];
    const float* Wh   = (const float*)d_in[6];
    const float* bh   = (const float*)d_in[7];
    const float* cash = (const float*)d_in[8];
    float* out = (float*)d_out;

    int N = in_sizes[0] / IN_DIM;
    int E = in_sizes[1] / 2;
    const int* src = ei;
    const int* dst = ei + E;
    int M = N + 1;

    // CSR bucket build (reused by both layers)
    k_init<<<(N + 255) / 256, 256>>>(cash, N);
    k_count<<<(E + 255) / 256, 256>>>(dst, E);
    k_prep<<<(N + 255) / 256, 256>>>(N);
    k_fill<<<(E + 255) / 256, 256>>>(src, dst, E);

    // dense transform (needs dinv from prep)
    k_gemm1<<<(N + TILE - 1) / TILE, 256>>>(x, W1, N);

    // layer 1 propagate + fused gemm2
    k_gather1<<<(N + 7) / 8, 256>>>(W2, b1, N);
    // layer 2 propagate + fused head
    k_gather2<<<(N + 7) / 8, 256>>>(Wh, b2, bh, N);

    // softmax
    k_max<<<256, 256>>>(M);
    k_sumexp<<<256, 256>>>(M);
    k_norm<<<(M + 255) / 256, 256>>>(out, M);
}

// round 10
// speedup vs baseline: 2.1912x; 1.0192x over previous
#include <cuda_runtime.h>
#include <math.h>

#define N_MAX   100000
#define E_MAX   3300000
#define IN_DIM  128
#define HID     32
#define TILE    64
#define FULL    0xffffffffu

// ---- scratch (no allocation allowed) ----
__device__ __align__(16) float g_bufA[(size_t)N_MAX * HID];   // dinv * (x@W1)
__device__ __align__(16) float g_bufB[(size_t)N_MAX * HID];   // dinv * (h@W2)
__device__ float g_dinv[N_MAX];
__device__ int   g_cnt[N_MAX];      // in-degree (no self loop)
__device__ int   g_base[N_MAX];     // bucket base
__device__ int   g_esrc[E_MAX];     // bucketed src ids
__device__ int   g_eoff[E_MAX];     // per-edge offset within its dst bucket
__device__ int   g_total;
__device__ float g_scores[N_MAX + 1];
__device__ float g_max_v;
__device__ float g_sum_v;

// ============ init: zero counters, reset softmax state, scores[0]=cash ============
__global__ void k_init(const float* __restrict__ cash, int N) {
    int i = blockIdx.x * blockDim.x + threadIdx.x;
    if (i < N) g_cnt[i] = 0;
    if (i == 0) {
        g_total = 0;
        g_max_v = -INFINITY;
        g_sum_v = 0.0f;
        g_scores[0] = cash[0];
    }
}

// ============ count in-degree, record within-bucket offset (coalesced) ============
__global__ void k_count(const int* __restrict__ dst, int E) {
    int i = blockIdx.x * blockDim.x + threadIdx.x;
    if (i < E) g_eoff[i] = atomicAdd(&g_cnt[dst[i]], 1);
}

// ============ prep: dinv = rsqrt(deg), bucket bases via warp-scan ============
__global__ void k_prep(int N) {
    int i = blockIdx.x * blockDim.x + threadIdx.x;
    int lane = threadIdx.x & 31;
    int cnt = (i < N) ? g_cnt[i] : 0;
    if (i < N) g_dinv[i] = rsqrtf((float)(cnt + 1));   // +1 self-loop

    // warp inclusive scan of cnt
    int c = cnt;
    #pragma unroll
    for (int o = 1; o < 32; o <<= 1) {
        int t = __shfl_up_sync(FULL, c, o);
        if (lane >= o) c += t;
    }
    int warptot = __shfl_sync(FULL, c, 31);
    int excl = c - cnt;
    int wbase = 0;
    if (lane == 0) wbase = atomicAdd(&g_total, warptot);
    wbase = __shfl_sync(FULL, wbase, 0);
    if (i < N) g_base[i] = wbase + excl;
}

// ============ merged: odd blocks fill buckets, even blocks do GEMM1 ============
// fill:  g_esrc[base[dst]+eoff] = src   (atomic-free scatter, L2-bound)
// gemm1: bufA = dinv * (x @ W1)         (FMA/smem-bound)
// Disjoint resources -> co-run on SMs, hiding one under the other.
__global__ __launch_bounds__(256) void k_fill_gemm1(
    const int* __restrict__ src, const int* __restrict__ dst, int E,
    const float* __restrict__ x, const float* __restrict__ W1, int N)
{
    __shared__ float sW[IN_DIM * HID];                  // 16 KB
    __shared__ __align__(16) float sx[TILE * IN_DIM];   // 32 KB
    int half = gridDim.x >> 1;
    int role_b = blockIdx.x >> 1;

    if (blockIdx.x & 1) {
        // ---- fill role ----
        for (int i = role_b * blockDim.x + threadIdx.x; i < E;
             i += half * blockDim.x) {
            int d = dst[i];
            g_esrc[g_base[d] + g_eoff[i]] = src[i];
        }
        return;
    }

    // ---- gemm role ----
    for (int i = threadIdx.x; i < IN_DIM * HID; i += blockDim.x) sW[i] = W1[i];
    int warp = threadIdx.x >> 5, lane = threadIdx.x & 31;

    for (int tile = role_b * TILE; tile < N; tile += half * TILE) {
        __syncthreads();
        int rows = min(TILE, N - tile);
        for (int i = threadIdx.x; i < rows * (IN_DIM / 4); i += blockDim.x) {
            int r = i >> 5, c = i & 31;
            ((float4*)sx)[r * 32 + c] =
                ((const float4*)(x + (size_t)(tile + r) * IN_DIM))[c];
        }
        __syncthreads();

        const float4* xr = (const float4*)(sx + warp * 8 * IN_DIM);
        float acc[8] = {0.f, 0.f, 0.f, 0.f, 0.f, 0.f, 0.f, 0.f};
        #pragma unroll
        for (int k4 = 0; k4 < IN_DIM / 4; k4++) {
            const float* wp = sW + k4 * 4 * HID + lane;
            float w0 = wp[0], w1 = wp[HID], w2 = wp[2 * HID], w3 = wp[3 * HID];
            #pragma unroll
            for (int i = 0; i < 8; i++) {
                float4 a = xr[i * 32 + k4];     // broadcast within warp
                acc[i] = fmaf(a.x, w0, acc[i]);
                acc[i] = fmaf(a.y, w1, acc[i]);
                acc[i] = fmaf(a.z, w2, acc[i]);
                acc[i] = fmaf(a.w, w3, acc[i]);
            }
        }
        #pragma unroll
        for (int i = 0; i < 8; i++) {
            int n = tile + warp * 8 + i;
            if (n < N) g_bufA[(size_t)n * HID + lane] = g_dinv[n] * acc[i];
        }
    }
}

// ============ gather core: returns bufX[d] + sum_e bufX[src_e]  (per-lane channel) ============
__device__ __forceinline__ float gather_row(const float* __restrict__ from,
                                            int d, int lane) {
    int base = g_base[d], cnt = g_cnt[d];
    float acc = from[(size_t)d * HID + lane];
    for (int j0 = 0; j0 < cnt; j0 += 32) {
        int jn = min(32, cnt - j0);
        int s = 0;
        if (lane < jn) s = g_esrc[base + j0 + lane];
        int j = 0;
        for (; j + 8 <= jn; j += 8) {
            int s0 = __shfl_sync(FULL, s, j);
            int s1 = __shfl_sync(FULL, s, j + 1);
            int s2 = __shfl_sync(FULL, s, j + 2);
            int s3 = __shfl_sync(FULL, s, j + 3);
            int s4 = __shfl_sync(FULL, s, j + 4);
            int s5 = __shfl_sync(FULL, s, j + 5);
            int s6 = __shfl_sync(FULL, s, j + 6);
            int s7 = __shfl_sync(FULL, s, j + 7);
            float v0 = from[(size_t)s0 * HID + lane];
            float v1 = from[(size_t)s1 * HID + lane];
            float v2 = from[(size_t)s2 * HID + lane];
            float v3 = from[(size_t)s3 * HID + lane];
            float v4 = from[(size_t)s4 * HID + lane];
            float v5 = from[(size_t)s5 * HID + lane];
            float v6 = from[(size_t)s6 * HID + lane];
            float v7 = from[(size_t)s7 * HID + lane];
            acc += ((v0 + v1) + (v2 + v3)) + ((v4 + v5) + (v6 + v7));
        }
        for (; j < jn; j++) {
            int sj = __shfl_sync(FULL, s, j);
            acc += from[(size_t)sj * HID + lane];
        }
    }
    return acc;
}

// ============ gather1 + fused gemm2: bufB = dinv * (relu(dinv*sum + b1) @ W2) ============
__global__ void k_gather1(const float* __restrict__ W2, const float* __restrict__ b1, int N) {
    __shared__ float sW[HID * HID];
    for (int i = threadIdx.x; i < HID * HID; i += blockDim.x) sW[i] = W2[i];
    __syncthreads();

    int lane = threadIdx.x & 31;
    int gwarp = blockIdx.x * (blockDim.x >> 5) + (threadIdx.x >> 5);
    int nw = gridDim.x * (blockDim.x >> 5);
    float bb = b1[lane];

    for (int d = gwarp; d < N; d += nw) {
        float t = gather_row(g_bufA, d, lane);
        float dd = g_dinv[d];
        float h = fmaxf(fmaf(dd, t, bb), 0.0f);
        float o = 0.0f;
        #pragma unroll
        for (int k = 0; k < HID; k++) {
            float hk = __shfl_sync(FULL, h, k);
            o = fmaf(hk, sW[k * HID + lane], o);
        }
        g_bufB[(size_t)d * HID + lane] = dd * o;
    }
}

// ============ gather2 + fused head: scores[d+1] = relu(dinv*sum+b2).Wh + bh ============
__global__ void k_gather2(const float* __restrict__ Wh, const float* __restrict__ b2,
                          const float* __restrict__ bh, int N) {
    int lane = threadIdx.x & 31;
    int gwarp = blockIdx.x * (blockDim.x >> 5) + (threadIdx.x >> 5);
    int nw = gridDim.x * (blockDim.x >> 5);
    float bb = b2[lane], wh = Wh[lane], bhv = bh[0];

    for (int d = gwarp; d < N; d += nw) {
        float t = gather_row(g_bufB, d, lane);
        float dd = g_dinv[d];
        float v = fmaxf(fmaf(dd, t, bb), 0.0f) * wh;
        #pragma unroll
        for (int o = 16; o > 0; o >>= 1) v += __shfl_xor_sync(FULL, v, o);
        if (lane == 0) g_scores[d + 1] = v + bhv;
    }
}

// ============ softmax ============
__device__ __forceinline__ void atomicMaxF(float* addr, float v) {
    if (v >= 0.0f) atomicMax((int*)addr, __float_as_int(v));
    else           atomicMin((unsigned int*)addr, __float_as_uint(v));
}

__global__ void k_max(int M) {
    float m = -INFINITY;
    for (int i = blockIdx.x * blockDim.x + threadIdx.x; i < M; i += gridDim.x * blockDim.x)
        m = fmaxf(m, g_scores[i]);
    #pragma unroll
    for (int o = 16; o > 0; o >>= 1) m = fmaxf(m, __shfl_xor_sync(FULL, m, o));
    __shared__ float sm[32];
    if ((threadIdx.x & 31) == 0) sm[threadIdx.x >> 5] = m;
    __syncthreads();
    if (threadIdx.x < 32) {
        float v = (threadIdx.x < (blockDim.x >> 5)) ? sm[threadIdx.x] : -INFINITY;
        #pragma unroll
        for (int o = 16; o > 0; o >>= 1) v = fmaxf(v, __shfl_xor_sync(FULL, v, o));
        if (threadIdx.x == 0) atomicMaxF(&g_max_v, v);
    }
}

__global__ void k_sumexp(int M) {
    float mx = g_max_v;
    float s = 0.0f;
    for (int i = blockIdx.x * blockDim.x + threadIdx.x; i < M; i += gridDim.x * blockDim.x)
        s += expf(g_scores[i] - mx);
    #pragma unroll
    for (int o = 16; o > 0; o >>= 1) s += __shfl_xor_sync(FULL, s, o);
    __shared__ float sm[32];
    if ((threadIdx.x & 31) == 0) sm[threadIdx.x >> 5] = s;
    __syncthreads();
    if (threadIdx.x < 32) {
        float v = (threadIdx.x < (blockDim.x >> 5)) ? sm[threadIdx.x] : 0.0f;
        #pragma unroll
        for (int o = 16; o > 0; o >>= 1) v += __shfl_xor_sync(FULL, v, o);
        if (threadIdx.x == 0) atomicAdd(&g_sum_v, v);
    }
}

__global__ void k_norm(float* __restrict__ out, int M) {
    float mx = g_max_v;
    float inv = 1.0f / g_sum_v;
    for (int i = blockIdx.x * blockDim.x + threadIdx.x; i < M; i += gridDim.x * blockDim.x)
        out[i] = expf(g_scores[i] - mx) * inv;
}

// ============ launch ============
extern "C" void kernel_launch(void* const* d_in, const int* in_sizes, int n_in,
                              void* d_out, int out_size) {
    const float* x    = (const float*)d_in[0];
    const int*   ei   = (const int*)d_in[1];     // int32 (JAX x64 disabled)
    const float* W1   = (const float*)d_in[2];
    const float* b1   = (const float*)d_in[3];
    const float* W2   = (const float*)d_in[4];
    const float* b2   = (const float*)d_in[5];
    const float* Wh   = (const float*)d_in[6];
    const float* bh   = (const float*)d_in[7];
    const float* cash = (const float*)d_in[8];
    float* out = (float*)d_out;

    int N = in_sizes[0] / IN_DIM;
    int E = in_sizes[1] / 2;
    const int* src = ei;
    const int* dst = ei + E;
    int M = N + 1;

    // CSR bucket build
    k_init<<<(N + 255) / 256, 256>>>(cash, N);
    k_count<<<(E + 255) / 256, 256>>>(dst, E);
    k_prep<<<(N + 255) / 256, 256>>>(N);

    // fill (odd blocks) co-running with gemm1 (even blocks)
    int gemm_blocks = (N + TILE - 1) / TILE;          // 1563
    k_fill_gemm1<<<2 * gemm_blocks, 256>>>(src, dst, E, x, W1, N);

    // layer 1 propagate + fused gemm2
    k_gather1<<<(N + 7) / 8, 256>>>(W2, b1, N);
    // layer 2 propagate + fused head
    k_gather2<<<(N + 7) / 8, 256>>>(Wh, b2, bh, N);

    // softmax
    k_max<<<256, 256>>>(M);
    k_sumexp<<<256, 256>>>(M);
    k_norm<<<(M + 255) / 256, 256>>>(out, M);
}

// round 11
// speedup vs baseline: 2.3437x; 1.0696x over previous
#include <cuda_runtime.h>
#include <math.h>

#define N_MAX   100000
#define E_MAX   3300000
#define IN_DIM  128
#define HID     32
#define TILE    32
#define FULL    0xffffffffu

// ---- scratch (no allocation allowed) ----
__device__ __align__(16) float g_bufA[(size_t)N_MAX * HID];   // dinv * (x@W1)
__device__ __align__(16) float g_bufB[(size_t)N_MAX * HID];   // dinv * (h@W2)
__device__ float g_dinv[N_MAX];
__device__ int   g_cnt[N_MAX];      // in-degree (no self loop)
__device__ int   g_base[N_MAX];     // bucket base
__device__ int   g_esrc[E_MAX];     // bucketed src ids
__device__ int   g_eoff[E_MAX];     // per-edge offset within its dst bucket
__device__ int   g_total;
__device__ float g_scores[N_MAX + 1];
__device__ float g_max_v;
__device__ float g_sum_v;

// ============ init ============
__global__ void k_init(const float* __restrict__ cash, int N) {
    int i = blockIdx.x * blockDim.x + threadIdx.x;
    if (i < N) g_cnt[i] = 0;
    if (i == 0) {
        g_total = 0;
        g_max_v = -INFINITY;
        g_sum_v = 0.0f;
        g_scores[0] = cash[0];
    }
}

// ============ count in-degree, record within-bucket offset (coalesced) ============
__global__ void k_count(const int* __restrict__ dst, int E) {
    int i = blockIdx.x * blockDim.x + threadIdx.x;
    if (i < E) g_eoff[i] = atomicAdd(&g_cnt[dst[i]], 1);
}

// ============ prep: dinv = rsqrt(deg), bucket bases via warp-scan ============
__global__ void k_prep(int N) {
    int i = blockIdx.x * blockDim.x + threadIdx.x;
    int lane = threadIdx.x & 31;
    int cnt = (i < N) ? g_cnt[i] : 0;
    if (i < N) g_dinv[i] = rsqrtf((float)(cnt + 1));   // +1 self-loop

    int c = cnt;
    #pragma unroll
    for (int o = 1; o < 32; o <<= 1) {
        int t = __shfl_up_sync(FULL, c, o);
        if (lane >= o) c += t;
    }
    int warptot = __shfl_sync(FULL, c, 31);
    int excl = c - cnt;
    int wbase = 0;
    if (lane == 0) wbase = atomicAdd(&g_total, warptot);
    wbase = __shfl_sync(FULL, wbase, 0);
    if (i < N) g_base[i] = wbase + excl;
}

// ============ merged: odd blocks fill buckets, even blocks do GEMM1 ============
// 32 KB smem -> ~6-7 blocks/SM so the fill half keeps occupancy.
__global__ __launch_bounds__(256) void k_fill_gemm1(
    const int* __restrict__ src, const int* __restrict__ dst, int E,
    const float* __restrict__ x, const float* __restrict__ W1, int N)
{
    __shared__ float sW[IN_DIM * HID];                  // 16 KB
    __shared__ __align__(16) float sx[TILE * IN_DIM];   // 16 KB
    int half = gridDim.x >> 1;
    int role_b = blockIdx.x >> 1;

    if (blockIdx.x & 1) {
        // ---- fill role (atomic-free scatter) ----
        for (int i = role_b * blockDim.x + threadIdx.x; i < E;
             i += half * blockDim.x) {
            int d = dst[i];
            g_esrc[g_base[d] + g_eoff[i]] = src[i];
        }
        return;
    }

    // ---- gemm role: 8 warps x 4 nodes, bufA = dinv * (x @ W1) ----
    for (int i = threadIdx.x; i < IN_DIM * HID; i += blockDim.x) sW[i] = W1[i];
    int warp = threadIdx.x >> 5, lane = threadIdx.x & 31;

    for (int tile = role_b * TILE; tile < N; tile += half * TILE) {
        __syncthreads();
        int rows = min(TILE, N - tile);
        for (int i = threadIdx.x; i < rows * (IN_DIM / 4); i += blockDim.x) {
            int r = i >> 5, c = i & 31;
            ((float4*)sx)[r * 32 + c] =
                ((const float4*)(x + (size_t)(tile + r) * IN_DIM))[c];
        }
        __syncthreads();

        const float4* x0 = (const float4*)(sx + (warp * 4 + 0) * IN_DIM);
        const float4* x1 = (const float4*)(sx + (warp * 4 + 1) * IN_DIM);
        const float4* x2 = (const float4*)(sx + (warp * 4 + 2) * IN_DIM);
        const float4* x3 = (const float4*)(sx + (warp * 4 + 3) * IN_DIM);
        float acc0 = 0.f, acc1 = 0.f, acc2 = 0.f, acc3 = 0.f;
        #pragma unroll
        for (int k4 = 0; k4 < IN_DIM / 4; k4++) {
            float4 a = x0[k4], b = x1[k4], c = x2[k4], d = x3[k4];
            const float* wp = sW + k4 * 4 * HID + lane;
            float w0 = wp[0], w1 = wp[HID], w2 = wp[2 * HID], w3 = wp[3 * HID];
            acc0 = fmaf(a.x, w0, acc0); acc1 = fmaf(b.x, w0, acc1);
            acc2 = fmaf(c.x, w0, acc2); acc3 = fmaf(d.x, w0, acc3);
            acc0 = fmaf(a.y, w1, acc0); acc1 = fmaf(b.y, w1, acc1);
            acc2 = fmaf(c.y, w1, acc2); acc3 = fmaf(d.y, w1, acc3);
            acc0 = fmaf(a.z, w2, acc0); acc1 = fmaf(b.z, w2, acc1);
            acc2 = fmaf(c.z, w2, acc2); acc3 = fmaf(d.z, w2, acc3);
            acc0 = fmaf(a.w, w3, acc0); acc1 = fmaf(b.w, w3, acc1);
            acc2 = fmaf(c.w, w3, acc2); acc3 = fmaf(d.w, w3, acc3);
        }

        float accs[4] = {acc0, acc1, acc2, acc3};
        #pragma unroll
        for (int i = 0; i < 4; i++) {
            int n = tile + warp * 4 + i;
            if (n < N) g_bufA[(size_t)n * HID + lane] = g_dinv[n] * accs[i];
        }
    }
}

// ============ gather core with smem-staged indices ============
// sIdx: per-warp 32-int slot. 1 coalesced LDG + 1 STS per batch, then
// uniform int4 LDS broadcasts (2 LDS.128 per 8 edges) replace shuffles.
__device__ __forceinline__ float gather_row(const float* __restrict__ from,
                                            int d, int lane, int* __restrict__ sIdx) {
    int base = g_base[d], cnt = g_cnt[d];
    float acc = from[(size_t)d * HID + lane];
    for (int j0 = 0; j0 < cnt; j0 += 32) {
        int jn = min(32, cnt - j0);
        if (lane < jn) sIdx[lane] = g_esrc[base + j0 + lane];
        __syncwarp();
        int j = 0;
        for (; j + 8 <= jn; j += 8) {
            int4 ia = *(const int4*)(sIdx + j);
            int4 ib = *(const int4*)(sIdx + j + 4);
            float v0 = from[(size_t)ia.x * HID + lane];
            float v1 = from[(size_t)ia.y * HID + lane];
            float v2 = from[(size_t)ia.z * HID + lane];
            float v3 = from[(size_t)ia.w * HID + lane];
            float v4 = from[(size_t)ib.x * HID + lane];
            float v5 = from[(size_t)ib.y * HID + lane];
            float v6 = from[(size_t)ib.z * HID + lane];
            float v7 = from[(size_t)ib.w * HID + lane];
            acc += ((v0 + v1) + (v2 + v3)) + ((v4 + v5) + (v6 + v7));
        }
        for (; j < jn; j++)
            acc += from[(size_t)sIdx[j] * HID + lane];
        __syncwarp();
    }
    return acc;
}

// ============ gather1 + fused gemm2: bufB = dinv * (relu(dinv*sum + b1) @ W2) ============
__global__ void k_gather1(const float* __restrict__ W2, const float* __restrict__ b1, int N) {
    __shared__ float sW[HID * HID];
    __shared__ __align__(16) int sIdxAll[8][32];
    for (int i = threadIdx.x; i < HID * HID; i += blockDim.x) sW[i] = W2[i];
    __syncthreads();

    int lane = threadIdx.x & 31;
    int warp = threadIdx.x >> 5;
    int* sIdx = sIdxAll[warp];
    int gwarp = blockIdx.x * (blockDim.x >> 5) + warp;
    int nw = gridDim.x * (blockDim.x >> 5);
    float bb = b1[lane];

    for (int d = gwarp; d < N; d += nw) {
        float t = gather_row(g_bufA, d, lane, sIdx);
        float dd = g_dinv[d];
        float h = fmaxf(fmaf(dd, t, bb), 0.0f);
        float o = 0.0f;
        #pragma unroll
        for (int k = 0; k < HID; k++) {
            float hk = __shfl_sync(FULL, h, k);
            o = fmaf(hk, sW[k * HID + lane], o);
        }
        g_bufB[(size_t)d * HID + lane] = dd * o;
    }
}

// ============ gather2 + fused head: scores[d+1] = relu(dinv*sum+b2).Wh + bh ============
__global__ void k_gather2(const float* __restrict__ Wh, const float* __restrict__ b2,
                          const float* __restrict__ bh, int N) {
    __shared__ __align__(16) int sIdxAll[8][32];
    int lane = threadIdx.x & 31;
    int warp = threadIdx.x >> 5;
    int* sIdx = sIdxAll[warp];
    int gwarp = blockIdx.x * (blockDim.x >> 5) + warp;
    int nw = gridDim.x * (blockDim.x >> 5);
    float bb = b2[lane], wh = Wh[lane], bhv = bh[0];

    for (int d = gwarp; d < N; d += nw) {
        float t = gather_row(g_bufB, d, lane, sIdx);
        float dd = g_dinv[d];
        float v = fmaxf(fmaf(dd, t, bb), 0.0f) * wh;
        #pragma unroll
        for (int o = 16; o > 0; o >>= 1) v += __shfl_xor_sync(FULL, v, o);
        if (lane == 0) g_scores[d + 1] = v + bhv;
    }
}

// ============ softmax ============
__device__ __forceinline__ void atomicMaxF(float* addr, float v) {
    if (v >= 0.0f) atomicMax((int*)addr, __float_as_int(v));
    else           atomicMin((unsigned int*)addr, __float_as_uint(v));
}

__global__ void k_max(int M) {
    float m = -INFINITY;
    for (int i = blockIdx.x * blockDim.x + threadIdx.x; i < M; i += gridDim.x * blockDim.x)
        m = fmaxf(m, g_scores[i]);
    #pragma unroll
    for (int o = 16; o > 0; o >>= 1) m = fmaxf(m, __shfl_xor_sync(FULL, m, o));
    __shared__ float sm[32];
    if ((threadIdx.x & 31) == 0) sm[threadIdx.x >> 5] = m;
    __syncthreads();
    if (threadIdx.x < 32) {
        float v = (threadIdx.x < (blockDim.x >> 5)) ? sm[threadIdx.x] : -INFINITY;
        #pragma unroll
        for (int o = 16; o > 0; o >>= 1) v = fmaxf(v, __shfl_xor_sync(FULL, v, o));
        if (threadIdx.x == 0) atomicMaxF(&g_max_v, v);
    }
}

__global__ void k_sumexp(int M) {
    float mx = g_max_v;
    float s = 0.0f;
    for (int i = blockIdx.x * blockDim.x + threadIdx.x; i < M; i += gridDim.x * blockDim.x)
        s += expf(g_scores[i] - mx);
    #pragma unroll
    for (int o = 16; o > 0; o >>= 1) s += __shfl_xor_sync(FULL, s, o);
    __shared__ float sm[32];
    if ((threadIdx.x & 31) == 0) sm[threadIdx.x >> 5] = s;
    __syncthreads();
    if (threadIdx.x < 32) {
        float v = (threadIdx.x < (blockDim.x >> 5)) ? sm[threadIdx.x] : 0.0f;
        #pragma unroll
        for (int o = 16; o > 0; o >>= 1) v += __shfl_xor_sync(FULL, v, o);
        if (threadIdx.x == 0) atomicAdd(&g_sum_v, v);
    }
}

__global__ void k_norm(float* __restrict__ out, int M) {
    float mx = g_max_v;
    float inv = 1.0f / g_sum_v;
    for (int i = blockIdx.x * blockDim.x + threadIdx.x; i < M; i += gridDim.x * blockDim.x)
        out[i] = expf(g_scores[i] - mx) * inv;
}

// ============ launch ============
extern "C" void kernel_launch(void* const* d_in, const int* in_sizes, int n_in,
                              void* d_out, int out_size) {
    const float* x    = (const float*)d_in[0];
    const int*   ei   = (const int*)d_in[1];     // int32 (JAX x64 disabled)
    const float* W1   = (const float*)d_in[2];
    const float* b1   = (const float*)d_in[3];
    const float* W2   = (const float*)d_in[4];
    const float* b2   = (const float*)d_in[5];
    const float* Wh   = (const float*)d_in[6];
    const float* bh   = (const float*)d_in[7];
    const float* cash = (const float*)d_in[8];
    float* out = (float*)d_out;

    int N = in_sizes[0] / IN_DIM;
    int E = in_sizes[1] / 2;
    const int* src = ei;
    const int* dst = ei + E;
    int M = N + 1;

    // CSR bucket build
    k_init<<<(N + 255) / 256, 256>>>(cash, N);
    k_count<<<(E + 255) / 256, 256>>>(dst, E);
    k_prep<<<(N + 255) / 256, 256>>>(N);

    // fill (odd blocks) co-running with gemm1 (even blocks)
    int gemm_blocks = (N + TILE - 1) / TILE;          // 3125
    k_fill_gemm1<<<2 * gemm_blocks, 256>>>(src, dst, E, x, W1, N);

    // layer 1 propagate + fused gemm2
    k_gather1<<<(N + 7) / 8, 256>>>(W2, b1, N);
    // layer 2 propagate + fused head
    k_gather2<<<(N + 7) / 8, 256>>>(Wh, b2, bh, N);

    // softmax
    k_max<<<256, 256>>>(M);
    k_sumexp<<<256, 256>>>(M);
    k_norm<<<(M + 255) / 256, 256>>>(out, M);
}

// round 14
// speedup vs baseline: 2.4756x; 1.0563x over previous
#include <cuda_runtime.h>
#include <cuda_fp16.h>
#include <math.h>

#define N_MAX   100000
#define E_MAX   3300000
#define IN_DIM  128
#define HID     32
#define TILE    32
#define FULL    0xffffffffu

// ---- scratch (no allocation allowed) ----
__device__ __align__(16) __half g_hA[(size_t)N_MAX * HID];   // fp16: dinv * (x@W1)
__device__ __align__(16) __half g_hB[(size_t)N_MAX * HID];   // fp16: dinv * (h@W2)
__device__ float g_dinv[N_MAX];
__device__ int   g_cnt[N_MAX];      // in-degree (no self loop)
__device__ int   g_base[N_MAX];     // bucket base
__device__ int   g_esrc[E_MAX];     // bucketed src ids
__device__ int   g_eoff[E_MAX];     // per-edge offset within its dst bucket
__device__ int   g_total;
__device__ float g_scores[N_MAX + 1];
__device__ float g_max_v;
__device__ float g_sum_v;

// ============ init ============
__global__ void k_init(const float* __restrict__ cash, int N) {
    int i = blockIdx.x * blockDim.x + threadIdx.x;
    if (i < N) g_cnt[i] = 0;
    if (i == 0) {
        g_total = 0;
        g_max_v = -INFINITY;
        g_sum_v = 0.0f;
        g_scores[0] = cash[0];
    }
}

// ============ count in-degree, record within-bucket offset (coalesced) ============
__global__ void k_count(const int* __restrict__ dst, int E) {
    int i = blockIdx.x * blockDim.x + threadIdx.x;
    if (i < E) g_eoff[i] = atomicAdd(&g_cnt[dst[i]], 1);
}

// ============ prep: dinv = rsqrt(deg), bucket bases via warp-scan ============
__global__ void k_prep(int N) {
    int i = blockIdx.x * blockDim.x + threadIdx.x;
    int lane = threadIdx.x & 31;
    int cnt = (i < N) ? g_cnt[i] : 0;
    if (i < N) g_dinv[i] = rsqrtf((float)(cnt + 1));   // +1 self-loop

    int c = cnt;
    #pragma unroll
    for (int o = 1; o < 32; o <<= 1) {
        int t = __shfl_up_sync(FULL, c, o);
        if (lane >= o) c += t;
    }
    int warptot = __shfl_sync(FULL, c, 31);
    int excl = c - cnt;
    int wbase = 0;
    if (lane == 0) wbase = atomicAdd(&g_total, warptot);
    wbase = __shfl_sync(FULL, wbase, 0);
    if (i < N) g_base[i] = wbase + excl;
}

// ============ merged: odd blocks fill buckets, even blocks do GEMM1 ============
__global__ __launch_bounds__(256) void k_fill_gemm1(
    const int* __restrict__ src, const int* __restrict__ dst, int E,
    const float* __restrict__ x, const float* __restrict__ W1, int N)
{
    __shared__ float sW[IN_DIM * HID];                  // 16 KB
    __shared__ __align__(16) float sx[TILE * IN_DIM];   // 16 KB
    int half = gridDim.x >> 1;
    int role_b = blockIdx.x >> 1;

    if (blockIdx.x & 1) {
        // ---- fill role (atomic-free scatter) ----
        for (int i = role_b * blockDim.x + threadIdx.x; i < E;
             i += half * blockDim.x) {
            int d = dst[i];
            g_esrc[g_base[d] + g_eoff[i]] = src[i];
        }
        return;
    }

    // ---- gemm role: 8 warps x 4 nodes, hA = fp16(dinv * (x @ W1)) ----
    for (int i = threadIdx.x; i < IN_DIM * HID; i += blockDim.x) sW[i] = W1[i];
    int warp = threadIdx.x >> 5, lane = threadIdx.x & 31;

    for (int tile = role_b * TILE; tile < N; tile += half * TILE) {
        __syncthreads();
        int rows = min(TILE, N - tile);
        for (int i = threadIdx.x; i < rows * (IN_DIM / 4); i += blockDim.x) {
            int r = i >> 5, c = i & 31;
            ((float4*)sx)[r * 32 + c] =
                ((const float4*)(x + (size_t)(tile + r) * IN_DIM))[c];
        }
        __syncthreads();

        const float4* x0 = (const float4*)(sx + (warp * 4 + 0) * IN_DIM);
        const float4* x1 = (const float4*)(sx + (warp * 4 + 1) * IN_DIM);
        const float4* x2 = (const float4*)(sx + (warp * 4 + 2) * IN_DIM);
        const float4* x3 = (const float4*)(sx + (warp * 4 + 3) * IN_DIM);
        float acc0 = 0.f, acc1 = 0.f, acc2 = 0.f, acc3 = 0.f;
        #pragma unroll
        for (int k4 = 0; k4 < IN_DIM / 4; k4++) {
            float4 a = x0[k4], b = x1[k4], c = x2[k4], d = x3[k4];
            const float* wp = sW + k4 * 4 * HID + lane;
            float w0 = wp[0], w1 = wp[HID], w2 = wp[2 * HID], w3 = wp[3 * HID];
            acc0 = fmaf(a.x, w0, acc0); acc1 = fmaf(b.x, w0, acc1);
            acc2 = fmaf(c.x, w0, acc2); acc3 = fmaf(d.x, w0, acc3);
            acc0 = fmaf(a.y, w1, acc0); acc1 = fmaf(b.y, w1, acc1);
            acc2 = fmaf(c.y, w1, acc2); acc3 = fmaf(d.y, w1, acc3);
            acc0 = fmaf(a.z, w2, acc0); acc1 = fmaf(b.z, w2, acc1);
            acc2 = fmaf(c.z, w2, acc2); acc3 = fmaf(d.z, w2, acc3);
            acc0 = fmaf(a.w, w3, acc0); acc1 = fmaf(b.w, w3, acc1);
            acc2 = fmaf(c.w, w3, acc2); acc3 = fmaf(d.w, w3, acc3);
        }

        float accs[4] = {acc0, acc1, acc2, acc3};
        #pragma unroll
        for (int i = 0; i < 4; i++) {
            int n = tile + warp * 4 + i;
            if (n < N) g_hA[(size_t)n * HID + lane] = __float2half(g_dinv[n] * accs[i]);
        }
    }
}

// ============ fp16 gather core ============
// Warp per dst row. lanes 0-15 accumulate even-slot edges, lanes 16-31 odd-slot.
// Each lane loads one half2 = channel pair (lane&15). fp32 accumulation.
// Returns the per-lane channel value (channel == lane).
__device__ __forceinline__ float gather_row_h(const __half* __restrict__ fromh,
                                              int d, int lane, int* __restrict__ sIdx) {
    const __half2* from = (const __half2*)fromh;
    int base = g_base[d], cnt = g_cnt[d];
    int cp = lane & 15;          // channel-pair index
    int hid = lane >> 4;         // 0: even edges, 1: odd edges
    float ax = 0.f, ay = 0.f;
    if (hid == 0) {
        float2 t = __half22float2(from[(size_t)d * 16 + cp]);
        ax = t.x; ay = t.y;
    }
    for (int j0 = 0; j0 < cnt; j0 += 32) {
        int jn = min(32, cnt - j0);
        if (lane < jn) sIdx[lane] = g_esrc[base + j0 + lane];
        __syncwarp();
        int j = 0;
        for (; j + 8 <= jn; j += 8) {
            int s0 = sIdx[j + hid];
            int s1 = sIdx[j + 2 + hid];
            int s2 = sIdx[j + 4 + hid];
            int s3 = sIdx[j + 6 + hid];
            float2 v0 = __half22float2(from[(size_t)s0 * 16 + cp]);
            float2 v1 = __half22float2(from[(size_t)s1 * 16 + cp]);
            float2 v2 = __half22float2(from[(size_t)s2 * 16 + cp]);
            float2 v3 = __half22float2(from[(size_t)s3 * 16 + cp]);
            ax += (v0.x + v1.x) + (v2.x + v3.x);
            ay += (v0.y + v1.y) + (v2.y + v3.y);
        }
        for (; j + 2 <= jn; j += 2) {
            int s = sIdx[j + hid];
            float2 v = __half22float2(from[(size_t)s * 16 + cp]);
            ax += v.x; ay += v.y;
        }
        if (j < jn && hid == 0) {          // odd leftover edge
            int s = sIdx[j];
            float2 v = __half22float2(from[(size_t)s * 16 + cp]);
            ax += v.x; ay += v.y;
        }
        __syncwarp();
    }
    // merge the two edge halves (lanes 0-15 get totals)
    ax += __shfl_down_sync(FULL, ax, 16);
    ay += __shfl_down_sync(FULL, ay, 16);
    // redistribute pairs -> per-lane channel: channel k lives in lane k>>1 (x if even, y if odd)
    float hx = __shfl_sync(FULL, ax, lane >> 1);
    float hy = __shfl_sync(FULL, ay, lane >> 1);
    return (lane & 1) ? hy : hx;
}

// ============ gather1 + fused gemm2: hB = fp16(dinv * (relu(dinv*sum + b1) @ W2)) ============
__global__ void k_gather1(const float* __restrict__ W2, const float* __restrict__ b1, int N) {
    __shared__ float sW[HID * HID];
    __shared__ __align__(16) int sIdxAll[8][32];
    for (int i = threadIdx.x; i < HID * HID; i += blockDim.x) sW[i] = W2[i];
    __syncthreads();

    int lane = threadIdx.x & 31;
    int warp = threadIdx.x >> 5;
    int* sIdx = sIdxAll[warp];
    int gwarp = blockIdx.x * (blockDim.x >> 5) + warp;
    int nw = gridDim.x * (blockDim.x >> 5);
    float bb = b1[lane];

    for (int d = gwarp; d < N; d += nw) {
        float t = gather_row_h(g_hA, d, lane, sIdx);
        float dd = g_dinv[d];
        float h = fmaxf(fmaf(dd, t, bb), 0.0f);
        float o = 0.0f;
        #pragma unroll
        for (int k = 0; k < HID; k++) {
            float hk = __shfl_sync(FULL, h, k);
            o = fmaf(hk, sW[k * HID + lane], o);
        }
        g_hB[(size_t)d * HID + lane] = __float2half(dd * o);
    }
}

// ============ gather2 + fused head: scores[d+1] = relu(dinv*sum+b2).Wh + bh ============
__global__ void k_gather2(const float* __restrict__ Wh, const float* __restrict__ b2,
                          const float* __restrict__ bh, int N) {
    __shared__ __align__(16) int sIdxAll[8][32];
    int lane = threadIdx.x & 31;
    int warp = threadIdx.x >> 5;
    int* sIdx = sIdxAll[warp];
    int gwarp = blockIdx.x * (blockDim.x >> 5) + warp;
    int nw = gridDim.x * (blockDim.x >> 5);
    float bb = b2[lane], wh = Wh[lane], bhv = bh[0];

    for (int d = gwarp; d < N; d += nw) {
        float t = gather_row_h(g_hB, d, lane, sIdx);
        float dd = g_dinv[d];
        float v = fmaxf(fmaf(dd, t, bb), 0.0f) * wh;
        #pragma unroll
        for (int o = 16; o > 0; o >>= 1) v += __shfl_xor_sync(FULL, v, o);
        if (lane == 0) g_scores[d + 1] = v + bhv;
    }
}

// ============ softmax ============
__device__ __forceinline__ void atomicMaxF(float* addr, float v) {
    if (v >= 0.0f) atomicMax((int*)addr, __float_as_int(v));
    else           atomicMin((unsigned int*)addr, __float_as_uint(v));
}

__global__ void k_max(int M) {
    float m = -INFINITY;
    for (int i = blockIdx.x * blockDim.x + threadIdx.x; i < M; i += gridDim.x * blockDim.x)
        m = fmaxf(m, g_scores[i]);
    #pragma unroll
    for (int o = 16; o > 0; o >>= 1) m = fmaxf(m, __shfl_xor_sync(FULL, m, o));
    __shared__ float sm[32];
    if ((threadIdx.x & 31) == 0) sm[threadIdx.x >> 5] = m;
    __syncthreads();
    if (threadIdx.x < 32) {
        float v = (threadIdx.x < (blockDim.x >> 5)) ? sm[threadIdx.x] : -INFINITY;
        #pragma unroll
        for (int o = 16; o > 0; o >>= 1) v = fmaxf(v, __shfl_xor_sync(FULL, v, o));
        if (threadIdx.x == 0) atomicMaxF(&g_max_v, v);
    }
}

__global__ void k_sumexp(int M) {
    float mx = g_max_v;
    float s = 0.0f;
    for (int i = blockIdx.x * blockDim.x + threadIdx.x; i < M; i += gridDim.x * blockDim.x)
        s += expf(g_scores[i] - mx);
    #pragma unroll
    for (int o = 16; o > 0; o >>= 1) s += __shfl_xor_sync(FULL, s, o);
    __shared__ float sm[32];
    if ((threadIdx.x & 31) == 0) sm[threadIdx.x >> 5] = s;
    __syncthreads();
    if (threadIdx.x < 32) {
        float v = (threadIdx.x < (blockDim.x >> 5)) ? sm[threadIdx.x] : 0.0f;
        #pragma unroll
        for (int o = 16; o > 0; o >>= 1) v += __shfl_xor_sync(FULL, v, o);
        if (threadIdx.x == 0) atomicAdd(&g_sum_v, v);
    }
}

__global__ void k_norm(float* __restrict__ out, int M) {
    float mx = g_max_v;
    float inv = 1.0f / g_sum_v;
    for (int i = blockIdx.x * blockDim.x + threadIdx.x; i < M; i += gridDim.x * blockDim.x)
        out[i] = expf(g_scores[i] - mx) * inv;
}

// ============ launch ============
extern "C" void kernel_launch(void* const* d_in, const int* in_sizes, int n_in,
                              void* d_out, int out_size) {
    const float* x    = (const float*)d_in[0];
    const int*   ei   = (const int*)d_in[1];     // int32 (JAX x64 disabled)
    const float* W1   = (const float*)d_in[2];
    const float* b1   = (const float*)d_in[3];
    const float* W2   = (const float*)d_in[4];
    const float* b2   = (const float*)d_in[5];
    const float* Wh   = (const float*)d_in[6];
    const float* bh   = (const float*)d_in[7];
    const float* cash = (const float*)d_in[8];
    float* out = (float*)d_out;

    int N = in_sizes[0] / IN_DIM;
    int E = in_sizes[1] / 2;
    const int* src = ei;
    const int* dst = ei + E;
    int M = N + 1;

    // CSR bucket build
    k_init<<<(N + 255) / 256, 256>>>(cash, N);
    k_count<<<(E + 255) / 256, 256>>>(dst, E);
    k_prep<<<(N + 255) / 256, 256>>>(N);

    // fill (odd blocks) co-running with gemm1 (even blocks)
    int gemm_blocks = (N + TILE - 1) / TILE;
    k_fill_gemm1<<<2 * gemm_blocks, 256>>>(src, dst, E, x, W1, N);

    // layer 1 propagate + fused gemm2
    k_gather1<<<(N + 7) / 8, 256>>>(W2, b1, N);
    // layer 2 propagate + fused head
    k_gather2<<<(N + 7) / 8, 256>>>(Wh, b2, bh, N);

    // softmax
    k_max<<<256, 256>>>(M);
    k_sumexp<<<256, 256>>>(M);
    k_norm<<<(M + 255) / 256, 256>>>(out, M);
}